// round 7
// baseline (speedup 1.0000x reference)
#include <cuda_runtime.h>
#include <cuda_bf16.h>
#include <stdint.h>

// ---------------- problem constants ----------------
#define BATCH  2
#define TQ     2048
#define CDIM   1024
#define NHEAD  16
#define DHEAD  64
#define C3     (3 * CDIM)
#define NQT2   (TQ / 128)
#define NROWS  (BATCH * NHEAD * TQ)
#define QKVN   (BATCH * NHEAD * TQ * DHEAD)

// ---------------- pre-split bf16 hi/lo planes (device scratch) ----------------
__device__ __align__(16) __nv_bfloat16 gXh[BATCH*TQ*CDIM],  gXl[BATCH*TQ*CDIM];
__device__ __align__(16) __nv_bfloat16 gWAh[CDIM*C3],       gWAl[CDIM*C3];
__device__ __align__(16) __nv_bfloat16 gWPh[CDIM*CDIM],     gWPl[CDIM*CDIM];
__device__ __align__(16) __nv_bfloat16 gQh[QKVN], gQl[QKVN];
__device__ __align__(16) __nv_bfloat16 gKh[QKVN], gKl[QKVN];
__device__ __align__(16) __nv_bfloat16 gVh[QKVN], gVl[QKVN];
__device__ __align__(16) __nv_bfloat16 gYh[BATCH*TQ*CDIM],  gYl[BATCH*TQ*CDIM];
__device__ float g_ent[BATCH * NHEAD * NQT2];

// ---------------- helpers ----------------
__device__ __forceinline__ void split2(float a, float b, unsigned& hi, unsigned& lo) {
    __nv_bfloat162 h = __floats2bfloat162_rn(a, b);
    float ra = a - __bfloat162float(h.x);
    float rb = b - __bfloat162float(h.y);
    __nv_bfloat162 l = __floats2bfloat162_rn(ra, rb);
    hi = *reinterpret_cast<unsigned*>(&h);
    lo = *reinterpret_cast<unsigned*>(&l);
}
// NOTE: NOT volatile — pure register compute; lets ptxas interleave
// independent accumulator chains (R7 change).
__device__ __forceinline__ void mma16(float* c, const unsigned* a, unsigned b0, unsigned b1) {
    asm("mma.sync.aligned.m16n8k16.row.col.f32.bf16.bf16.f32 "
        "{%0,%1,%2,%3},{%4,%5,%6,%7},{%8,%9},{%0,%1,%2,%3};"
        : "+f"(c[0]), "+f"(c[1]), "+f"(c[2]), "+f"(c[3])
        : "r"(a[0]), "r"(a[1]), "r"(a[2]), "r"(a[3]), "r"(b0), "r"(b1));
}
__device__ __forceinline__ void ldsm4(unsigned& r0, unsigned& r1, unsigned& r2, unsigned& r3, uint32_t a) {
    asm volatile("ldmatrix.sync.aligned.m8n8.x4.shared.b16 {%0,%1,%2,%3},[%4];"
        : "=r"(r0), "=r"(r1), "=r"(r2), "=r"(r3) : "r"(a));
}
__device__ __forceinline__ void ldsm4t(unsigned& r0, unsigned& r1, unsigned& r2, unsigned& r3, uint32_t a) {
    asm volatile("ldmatrix.sync.aligned.m8n8.x4.trans.shared.b16 {%0,%1,%2,%3},[%4];"
        : "=r"(r0), "=r"(r1), "=r"(r2), "=r"(r3) : "r"(a));
}
__device__ __forceinline__ void cpa16(uint32_t d, const void* s) {
    asm volatile("cp.async.ca.shared.global [%0],[%1],16;" :: "r"(d), "l"(s));
}
#define CP_COMMIT() asm volatile("cp.async.commit_group;" ::: "memory")
#define CP_WAIT(N)  asm volatile("cp.async.wait_group %0;" :: "n"(N) : "memory")

// =====================================================================
// prep: elementwise fp32 -> bf16 hi/lo planes
// =====================================================================
__global__ void split_kernel(const float* __restrict__ in,
                             __nv_bfloat16* __restrict__ hi,
                             __nv_bfloat16* __restrict__ lo, int n4)
{
    int i = blockIdx.x * blockDim.x + threadIdx.x;
    if (i < n4) {
        float4 v = ((const float4*)in)[i];
        unsigned h0, l0, h1, l1;
        split2(v.x, v.y, h0, l0); split2(v.z, v.w, h1, l1);
        ((uint2*)hi)[i] = make_uint2(h0, h1);
        ((uint2*)lo)[i] = make_uint2(l0, l1);
    }
}

// =====================================================================
// GEMM (pre-split bf16x3): C = A @ B. 128x128 tile, BK=32, 256 thr,
// 3-stage cp.async, ldmatrix frags, pass-major MMA interleave.
// =====================================================================
#define GSTG 32768
extern __shared__ char dsm[];

__device__ __forceinline__ void gemm_issue(
    uint32_t s0, const __nv_bfloat16* Ah, const __nv_bfloat16* Al,
    const __nv_bfloat16* Bh, const __nv_bfloat16* Bl,
    int bm, int bn, int k0, int K, int N, int tid)
{
#pragma unroll
    for (int it = 0; it < 2; it++) {
        int id = tid + it * 256;
        int r = id >> 2, c = id & 3;
        uint32_t d = s0 + r * 64 + ((c ^ ((r >> 1) & 3)) << 4);
        size_t go = (size_t)(bm + r) * K + k0 + c * 8;
        cpa16(d,        Ah + go);
        cpa16(d + 8192, Al + go);
    }
#pragma unroll
    for (int it = 0; it < 2; it++) {
        int id = tid + it * 256;
        int k = id >> 4, c = id & 15;
        uint32_t d = s0 + 16384 + k * 256 + ((c ^ (k & 7)) << 4);
        size_t go = (size_t)(k0 + k) * N + bn + c * 8;
        cpa16(d,        Bh + go);
        cpa16(d + 8192, Bl + go);
    }
}

__global__ __launch_bounds__(256, 2) void gemm_pre(
    const __nv_bfloat16* __restrict__ Ah, const __nv_bfloat16* __restrict__ Al,
    const __nv_bfloat16* __restrict__ Bh, const __nv_bfloat16* __restrict__ Bl,
    float* __restrict__ C, int M, int N, int K, int mode)
{
    const uint32_t sb = (uint32_t)__cvta_generic_to_shared(dsm);
    const int tid = threadIdx.x, lane = tid & 31, wid = tid >> 5;
    const int g = lane >> 2, t = lane & 3;
    const int m8 = lane >> 3, ri = lane & 7;
    const int wm = wid & 3, wn = wid >> 2;
    const int bm = blockIdx.y * 128, bn = blockIdx.x * 128;

    float acc[2][8][4];
#pragma unroll
    for (int mt = 0; mt < 2; mt++)
#pragma unroll
        for (int nt = 0; nt < 8; nt++)
#pragma unroll
            for (int i = 0; i < 4; i++) acc[mt][nt][i] = 0.f;

    const int NCH = K / 32;
    gemm_issue(sb,        Ah, Al, Bh, Bl, bm, bn, 0,  K, N, tid); CP_COMMIT();
    gemm_issue(sb + GSTG, Ah, Al, Bh, Bl, bm, bn, 32, K, N, tid); CP_COMMIT();

    for (int ch = 0; ch < NCH; ch++) {
        if (ch + 2 < NCH)
            gemm_issue(sb + ((ch + 2) % 3) * GSTG, Ah, Al, Bh, Bl,
                       bm, bn, (ch + 2) * 32, K, N, tid);
        CP_COMMIT();
        CP_WAIT(2);
        __syncthreads();

        const uint32_t s0 = sb + (ch % 3) * GSTG;
#pragma unroll
        for (int ks = 0; ks < 2; ks++) {
            unsigned ah[2][4], al[2][4];
#pragma unroll
            for (int mt = 0; mt < 2; mt++) {
                int row = wm * 32 + mt * 16 + (m8 & 1) * 8 + ri;
                int c4  = 2 * ks + (m8 >> 1);
                uint32_t a = s0 + row * 64 + ((c4 ^ ((row >> 1) & 3)) << 4);
                ldsm4(ah[mt][0], ah[mt][1], ah[mt][2], ah[mt][3], a);
                ldsm4(al[mt][0], al[mt][1], al[mt][2], al[mt][3], a + 8192);
            }
#pragma unroll
            for (int ntp = 0; ntp < 4; ntp++) {
                int kr = 16 * ks + (m8 & 1) * 8 + ri;
                int cc = wn * 8 + ntp * 2 + (m8 >> 1);
                uint32_t ba = s0 + 16384 + kr * 256 + ((cc ^ (kr & 7)) << 4);
                unsigned bh[4], bl[4];
                ldsm4t(bh[0], bh[1], bh[2], bh[3], ba);
                ldsm4t(bl[0], bl[1], bl[2], bl[3], ba + 8192);
                float* c00 = acc[0][ntp * 2 + 0];
                float* c10 = acc[1][ntp * 2 + 0];
                float* c01 = acc[0][ntp * 2 + 1];
                float* c11 = acc[1][ntp * 2 + 1];
                // pass-major: dependent-pair spacing = 4
                mma16(c00, ah[0], bh[0], bh[1]);
                mma16(c10, ah[1], bh[0], bh[1]);
                mma16(c01, ah[0], bh[2], bh[3]);
                mma16(c11, ah[1], bh[2], bh[3]);
                mma16(c00, al[0], bh[0], bh[1]);
                mma16(c10, al[1], bh[0], bh[1]);
                mma16(c01, al[0], bh[2], bh[3]);
                mma16(c11, al[1], bh[2], bh[3]);
                mma16(c00, ah[0], bl[0], bl[1]);
                mma16(c10, ah[1], bl[0], bl[1]);
                mma16(c01, ah[0], bl[2], bl[3]);
                mma16(c11, ah[1], bl[2], bl[3]);
            }
        }
        __syncthreads();
    }

    // ---- epilogue ----
    if (mode == 0) {
#pragma unroll
        for (int mt = 0; mt < 2; mt++) {
#pragma unroll
            for (int nt = 0; nt < 8; nt++) {
                const int row = bm + wm * 32 + mt * 16 + g;
                const int col = bn + wn * 64 + nt * 8 + 2 * t;
                *(float2*)&C[(size_t)row * N + col] =
                    make_float2(acc[mt][nt][0], acc[mt][nt][1]);
                *(float2*)&C[(size_t)(row + 8) * N + col] =
                    make_float2(acc[mt][nt][2], acc[mt][nt][3]);
            }
        }
    } else {
#pragma unroll
        for (int mt = 0; mt < 2; mt++) {
#pragma unroll
            for (int nt = 0; nt < 8; nt++) {
                const int row = bm + wm * 32 + mt * 16 + g;
                const int col = bn + wn * 64 + nt * 8 + 2 * t;
                const int sec = col >> 10, hh = (col >> 6) & 15, d = col & 63;
                const int bb = row >> 11, tok = row & 2047;
                size_t idx = (((size_t)bb * NHEAD + hh) * TQ + tok) * DHEAD + d;
                __nv_bfloat16* hp = sec == 0 ? gQh : (sec == 1 ? gKh : gVh);
                __nv_bfloat16* lp = sec == 0 ? gQl : (sec == 1 ? gKl : gVl);
                unsigned hw, lw;
                split2(acc[mt][nt][0], acc[mt][nt][1], hw, lw);
                *(unsigned*)&hp[idx] = hw; *(unsigned*)&lp[idx] = lw;
                split2(acc[mt][nt][2], acc[mt][nt][3], hw, lw);
                *(unsigned*)&hp[idx + 8 * DHEAD] = hw;
                *(unsigned*)&lp[idx + 8 * DHEAD] = lw;
            }
        }
    }
}

// =====================================================================
// Flash attention: 64KB smem, occ=2, pass-major MMA interleave.
// =====================================================================
#define FSTG 32768

__device__ __forceinline__ void flash_issue_kv(uint32_t s0, size_t base, int j, int tid)
{
#pragma unroll
    for (int it = 0; it < 2; it++) {
        int id = tid + it * 256;
        int r = id >> 3, c = id & 7;
        uint32_t d = s0 + r * 128 + ((c ^ (r & 7)) << 4);
        size_t go = base + (size_t)(j * 64 + r) * DHEAD + c * 8;
        cpa16(d,         gKh + go);
        cpa16(d + 8192,  gKl + go);
        cpa16(d + 16384, gVh + go);
        cpa16(d + 24576, gVl + go);
    }
}

__global__ __launch_bounds__(256, 2) void flash_pre()
{
    __shared__ float sred[64];
    const uint32_t sb = (uint32_t)__cvta_generic_to_shared(dsm);
    const int qt = (int)gridDim.x - 1 - (int)blockIdx.x;   // longest-first
    const int h = blockIdx.y, b = blockIdx.z;
    const int tid = threadIdx.x, lane = tid & 31, wid = tid >> 5;
    const int g = lane >> 2, t = lane & 3;
    const int m8 = lane >> 3, ri = lane & 7;
    const size_t base = (size_t)(b * NHEAD + h) * TQ * DHEAD;

    // ---- Q hi/lo cp.async into stage-1 region ----
#pragma unroll
    for (int it = 0; it < 4; it++) {
        int id = tid + it * 256;
        int r = id >> 3, c = id & 7;
        uint32_t d = sb + FSTG + r * 128 + ((c ^ (r & 7)) << 4);
        size_t go = base + (size_t)(qt * 128 + r) * DHEAD + c * 8;
        cpa16(d,         gQh + go);
        cpa16(d + 16384, gQl + go);
    }
    CP_COMMIT();
    flash_issue_kv(sb, base, 0, tid); CP_COMMIT();
    CP_WAIT(1);
    __syncthreads();

    // ---- hoist Q fragments ----
    unsigned qh[4][4], ql[4][4];
#pragma unroll
    for (int ks = 0; ks < 4; ks++) {
        int row = wid * 16 + (m8 & 1) * 8 + ri;
        int c = 2 * ks + (m8 >> 1);
        uint32_t a = sb + FSTG + row * 128 + ((c ^ (row & 7)) << 4);
        ldsm4(qh[ks][0], qh[ks][1], qh[ks][2], qh[ks][3], a);
        ldsm4(ql[ks][0], ql[ks][1], ql[ks][2], ql[ks][3], a + 16384);
    }
    __syncthreads();

    float oc[8][4];
#pragma unroll
    for (int nt = 0; nt < 8; nt++)
#pragma unroll
        for (int i = 0; i < 4; i++) oc[nt][i] = 0.f;

    float m0 = -1e30f, m1 = -1e30f, l0s = 0.f, l1s = 0.f, aa0 = 0.f, aa1 = 0.f;
    const int rowbase = qt * 128 + wid * 16;
    const int nj = 2 * qt + 2;

    for (int j = 0; j < nj; j++) {
        if (j + 1 < nj) flash_issue_kv(sb + ((j + 1) & 1) * FSTG, base, j + 1, tid);
        CP_COMMIT();
        CP_WAIT(1);
        __syncthreads();
        const uint32_t kv = sb + (j & 1) * FSTG;

        // ---- S = Q K^T ----
        float sc[8][4];
#pragma unroll
        for (int nt = 0; nt < 8; nt++)
#pragma unroll
            for (int i = 0; i < 4; i++) sc[nt][i] = 0.f;

#pragma unroll
        for (int ks = 0; ks < 4; ks++) {
#pragma unroll
            for (int ntp = 0; ntp < 4; ntp++) {
                int kr = ntp * 16 + (m8 & 1) * 8 + ri;
                int c = 2 * ks + (m8 >> 1);
                uint32_t ka = kv + kr * 128 + ((c ^ (kr & 7)) << 4);
                unsigned kh[4], kl[4];
                ldsm4(kh[0], kh[1], kh[2], kh[3], ka);
                ldsm4(kl[0], kl[1], kl[2], kl[3], ka + 8192);
                float* s0p = sc[2 * ntp];
                float* s1p = sc[2 * ntp + 1];
                // pass-major: dependent spacing = 2, cross-ntp independent
                mma16(s0p, qh[ks], kh[0], kh[2]);
                mma16(s1p, qh[ks], kh[1], kh[3]);
                mma16(s0p, ql[ks], kh[0], kh[2]);
                mma16(s1p, ql[ks], kh[1], kh[3]);
                mma16(s0p, qh[ks], kl[0], kl[2]);
                mma16(s1p, qh[ks], kl[1], kl[3]);
            }
        }

        // ---- scale + causal mask ----
        const bool needmask = (j * 64 + 63) > rowbase;
#pragma unroll
        for (int nt = 0; nt < 8; nt++) {
#pragma unroll
            for (int cc = 0; cc < 4; cc++) {
                float v = sc[nt][cc] * 0.125f;
                if (needmask) {
                    int col = j * 64 + nt * 8 + 2 * t + (cc & 1);
                    int row = rowbase + g + ((cc >> 1) << 3);
                    if (col > row) v = -1e30f;
                }
                sc[nt][cc] = v;
            }
        }

        // ---- online softmax + entropy ----
        float mt0 = -1e30f, mt1 = -1e30f;
#pragma unroll
        for (int nt = 0; nt < 8; nt++) {
            mt0 = fmaxf(mt0, fmaxf(sc[nt][0], sc[nt][1]));
            mt1 = fmaxf(mt1, fmaxf(sc[nt][2], sc[nt][3]));
        }
        mt0 = fmaxf(mt0, __shfl_xor_sync(0xffffffffu, mt0, 1));
        mt0 = fmaxf(mt0, __shfl_xor_sync(0xffffffffu, mt0, 2));
        mt1 = fmaxf(mt1, __shfl_xor_sync(0xffffffffu, mt1, 1));
        mt1 = fmaxf(mt1, __shfl_xor_sync(0xffffffffu, mt1, 2));

        const float mn0 = fmaxf(m0, mt0), mn1 = fmaxf(m1, mt1);
        const float ex0 = __expf(m0 - mn0), ex1 = __expf(m1 - mn1);

        float ls0 = 0.f, ls1 = 0.f, as0 = 0.f, as1 = 0.f;
#pragma unroll
        for (int nt = 0; nt < 8; nt++) {
            float s0 = sc[nt][0], s1 = sc[nt][1];
            float s2 = sc[nt][2], s3 = sc[nt][3];
            float p0 = __expf(s0 - mn0), p1 = __expf(s1 - mn0);
            float p2 = __expf(s2 - mn1), p3 = __expf(s3 - mn1);
            sc[nt][0] = p0; sc[nt][1] = p1; sc[nt][2] = p2; sc[nt][3] = p3;
            ls0 += p0 + p1;           ls1 += p2 + p3;
            as0 += p0 * s0 + p1 * s1; as1 += p2 * s2 + p3 * s3;
        }
        ls0 += __shfl_xor_sync(0xffffffffu, ls0, 1);
        ls0 += __shfl_xor_sync(0xffffffffu, ls0, 2);
        ls1 += __shfl_xor_sync(0xffffffffu, ls1, 1);
        ls1 += __shfl_xor_sync(0xffffffffu, ls1, 2);
        as0 += __shfl_xor_sync(0xffffffffu, as0, 1);
        as0 += __shfl_xor_sync(0xffffffffu, as0, 2);
        as1 += __shfl_xor_sync(0xffffffffu, as1, 1);
        as1 += __shfl_xor_sync(0xffffffffu, as1, 2);

        l0s = l0s * ex0 + ls0;  aa0 = aa0 * ex0 + as0;  m0 = mn0;
        l1s = l1s * ex1 + ls1;  aa1 = aa1 * ex1 + as1;  m1 = mn1;

#pragma unroll
        for (int nt = 0; nt < 8; nt++) {
            oc[nt][0] *= ex0; oc[nt][1] *= ex0;
            oc[nt][2] *= ex1; oc[nt][3] *= ex1;
        }

        // ---- pack P ----
        unsigned ph0[8], pl0[8], ph1[8], pl1[8];
#pragma unroll
        for (int nt = 0; nt < 8; nt++) {
            split2(sc[nt][0], sc[nt][1], ph0[nt], pl0[nt]);
            split2(sc[nt][2], sc[nt][3], ph1[nt], pl1[nt]);
        }

        // ---- O += P @ V ----
#pragma unroll
        for (int ks = 0; ks < 4; ks++) {
            unsigned aH[4] = {ph0[2*ks], ph1[2*ks], ph0[2*ks+1], ph1[2*ks+1]};
            unsigned aL[4] = {pl0[2*ks], pl1[2*ks], pl0[2*ks+1], pl1[2*ks+1]};
#pragma unroll
            for (int ntp = 0; ntp < 4; ntp++) {
                int vr = 16 * ks + (m8 & 1) * 8 + ri;
                int c = ntp * 2 + (m8 >> 1);
                uint32_t va = kv + 16384 + vr * 128 + ((c ^ (vr & 7)) << 4);
                unsigned vh[4], vl[4];
                ldsm4t(vh[0], vh[1], vh[2], vh[3], va);
                ldsm4t(vl[0], vl[1], vl[2], vl[3], va + 8192);
                float* o0 = oc[2 * ntp];
                float* o1 = oc[2 * ntp + 1];
                mma16(o0, aH, vh[0], vh[1]);
                mma16(o1, aH, vh[2], vh[3]);
                mma16(o0, aL, vh[0], vh[1]);
                mma16(o1, aL, vh[2], vh[3]);
                mma16(o0, aH, vl[0], vl[1]);
                mma16(o1, aH, vl[2], vl[3]);
            }
        }
        __syncthreads();
    }

    // ---- epilogue: write yatt hi/lo planes ----
    const float inv0 = 1.f / l0s, inv1 = 1.f / l1s;
    const int trow = rowbase + g;
#pragma unroll
    for (int nt = 0; nt < 8; nt++) {
        const int col = h * DHEAD + nt * 8 + 2 * t;
        size_t idx = ((size_t)b * TQ + trow) * CDIM + col;
        unsigned hw, lw;
        split2(oc[nt][0] * inv0, oc[nt][1] * inv0, hw, lw);
        *(unsigned*)&gYh[idx] = hw; *(unsigned*)&gYl[idx] = lw;
        split2(oc[nt][2] * inv1, oc[nt][3] * inv1, hw, lw);
        *(unsigned*)&gYh[idx + 8 * CDIM] = hw; *(unsigned*)&gYl[idx + 8 * CDIM] = lw;
    }

    // ---- entropy partial ----
    if (t == 0) {
        float H = (m0 + __logf(l0s) - aa0 / l0s) + (m1 + __logf(l1s) - aa1 / l1s);
        sred[wid * 8 + g] = H;
    }
    __syncthreads();
    if (tid == 0) {
        float s = 0.f;
#pragma unroll 8
        for (int r = 0; r < 64; r++) s += sred[r];
        g_ent[((size_t)b * NHEAD + h) * NQT2 + qt] = s;
    }
}

// =====================================================================
// entropy final reduction
// =====================================================================
__global__ void ent_final_kernel(float* __restrict__ out, int out_size)
{
    __shared__ float red[256];
    int tid = threadIdx.x;
    float s = 0.f;
    for (int i = tid; i < BATCH * NHEAD * NQT2; i += 256) s += g_ent[i];
    red[tid] = s;
    __syncthreads();
    for (int st = 128; st > 0; st >>= 1) {
        if (tid < st) red[tid] += red[tid + st];
        __syncthreads();
    }
    if (tid == 0) out[out_size - 1] = red[0] / (float)NROWS;
}

// =====================================================================
// launch
// =====================================================================
extern "C" void kernel_launch(void* const* d_in, const int* in_sizes, int n_in,
                              void* d_out, int out_size)
{
    const float* x      = (const float*)d_in[0];
    const float* w_attn = (const float*)d_in[1];
    const float* w_proj = (const float*)d_in[2];
    float* out = (float*)d_out;
    (void)in_sizes; (void)n_in;

    __nv_bfloat16 *xh, *xl, *wah, *wal, *wph, *wpl, *yh, *yl;
    cudaGetSymbolAddress((void**)&xh,  gXh);  cudaGetSymbolAddress((void**)&xl,  gXl);
    cudaGetSymbolAddress((void**)&wah, gWAh); cudaGetSymbolAddress((void**)&wal, gWAl);
    cudaGetSymbolAddress((void**)&wph, gWPh); cudaGetSymbolAddress((void**)&wpl, gWPl);
    cudaGetSymbolAddress((void**)&yh,  gYh);  cudaGetSymbolAddress((void**)&yl,  gYl);

    const int GEMM_SMEM  = 3 * GSTG;   // 98304
    const int FLASH_SMEM = 2 * FSTG;   // 65536
    cudaFuncSetAttribute(gemm_pre,
                         cudaFuncAttributeMaxDynamicSharedMemorySize, GEMM_SMEM);
    cudaFuncSetAttribute(flash_pre,
                         cudaFuncAttributeMaxDynamicSharedMemorySize, FLASH_SMEM);

    // 0) split inputs
    {
        int n4x = BATCH * TQ * CDIM / 4;
        split_kernel<<<(n4x + 255) / 256, 256>>>(x, xh, xl, n4x);
        int n4a = CDIM * C3 / 4;
        split_kernel<<<(n4a + 255) / 256, 256>>>(w_attn, wah, wal, n4a);
        int n4p = CDIM * CDIM / 4;
        split_kernel<<<(n4p + 255) / 256, 256>>>(w_proj, wph, wpl, n4p);
    }
    // 1) qkv = x @ w_attn  -> split qkv planes (mode 1)
    {
        dim3 grid(C3 / 128, (BATCH * TQ) / 128);
        gemm_pre<<<grid, 256, GEMM_SMEM>>>(xh, xl, wah, wal, nullptr,
                                           BATCH * TQ, C3, CDIM, 1);
    }
    // 2) flash attention + entropy partials -> gY planes
    {
        dim3 grid(NQT2, NHEAD, BATCH);
        flash_pre<<<grid, 256, FLASH_SMEM>>>();
    }
    // 3) y = yatt @ w_proj -> d_out (mode 0)
    {
        dim3 grid(CDIM / 128, (BATCH * TQ) / 128);
        gemm_pre<<<grid, 256, GEMM_SMEM>>>(yh, yl, wph, wpl, out,
                                           BATCH * TQ, CDIM, CDIM, 0);
    }
    // 4) entropy scalar
    ent_final_kernel<<<1, 256>>>(out, out_size);
}

// round 8
// speedup vs baseline: 1.3936x; 1.3936x over previous
#include <cuda_runtime.h>
#include <cuda_fp16.h>
#include <stdint.h>

// ---------------- problem constants ----------------
#define BATCH  2
#define TQ     2048
#define CDIM   1024
#define NHEAD  16
#define DHEAD  64
#define C3     (3 * CDIM)
#define NQT2   (TQ / 128)
#define NROWS  (BATCH * NHEAD * TQ)
#define QKVN   (BATCH * NHEAD * TQ * DHEAD)

// ---------------- fp16 planes (device scratch) ----------------
__device__ __align__(16) __half gXh[BATCH*TQ*CDIM], gXl[BATCH*TQ*CDIM];
__device__ __align__(16) __half gWA[CDIM*C3];
__device__ __align__(16) __half gWP[CDIM*CDIM];
__device__ __align__(16) __half gQh[QKVN], gQl[QKVN];
__device__ __align__(16) __half gK[QKVN];
__device__ __align__(16) __half gV[QKVN];
__device__ __align__(16) __half gYh[BATCH*TQ*CDIM], gYl[BATCH*TQ*CDIM];
__device__ float g_ent[BATCH * NHEAD * NQT2];

// ---------------- helpers ----------------
__device__ __forceinline__ void split2h(float a, float b, unsigned& hi, unsigned& lo) {
    __half2 h = __floats2half2_rn(a, b);
    float ra = a - __low2float(h);
    float rb = b - __high2float(h);
    __half2 l = __floats2half2_rn(ra, rb);
    hi = *reinterpret_cast<unsigned*>(&h);
    lo = *reinterpret_cast<unsigned*>(&l);
}
__device__ __forceinline__ unsigned round2h(float a, float b) {
    __half2 h = __floats2half2_rn(a, b);
    return *reinterpret_cast<unsigned*>(&h);
}
// fp16 m16n8k16 mma, fp32 accumulate (non-volatile: scheduler-free)
__device__ __forceinline__ void mma16(float* c, const unsigned* a, unsigned b0, unsigned b1) {
    asm("mma.sync.aligned.m16n8k16.row.col.f32.f16.f16.f32 "
        "{%0,%1,%2,%3},{%4,%5,%6,%7},{%8,%9},{%0,%1,%2,%3};"
        : "+f"(c[0]), "+f"(c[1]), "+f"(c[2]), "+f"(c[3])
        : "r"(a[0]), "r"(a[1]), "r"(a[2]), "r"(a[3]), "r"(b0), "r"(b1));
}
__device__ __forceinline__ void ldsm4(unsigned& r0, unsigned& r1, unsigned& r2, unsigned& r3, uint32_t a) {
    asm volatile("ldmatrix.sync.aligned.m8n8.x4.shared.b16 {%0,%1,%2,%3},[%4];"
        : "=r"(r0), "=r"(r1), "=r"(r2), "=r"(r3) : "r"(a));
}
__device__ __forceinline__ void ldsm4t(unsigned& r0, unsigned& r1, unsigned& r2, unsigned& r3, uint32_t a) {
    asm volatile("ldmatrix.sync.aligned.m8n8.x4.trans.shared.b16 {%0,%1,%2,%3},[%4];"
        : "=r"(r0), "=r"(r1), "=r"(r2), "=r"(r3) : "r"(a));
}
__device__ __forceinline__ void cpa16(uint32_t d, const void* s) {
    asm volatile("cp.async.ca.shared.global [%0],[%1],16;" :: "r"(d), "l"(s));
}
#define CP_COMMIT() asm volatile("cp.async.commit_group;" ::: "memory")
#define CP_WAIT(N)  asm volatile("cp.async.wait_group %0;" :: "n"(N) : "memory")

// =====================================================================
// prep kernels
// =====================================================================
__global__ void split_kernel(const float* __restrict__ in,
                             __half* __restrict__ hi, __half* __restrict__ lo, int n4)
{
    int i = blockIdx.x * blockDim.x + threadIdx.x;
    if (i < n4) {
        float4 v = ((const float4*)in)[i];
        unsigned h0, l0, h1, l1;
        split2h(v.x, v.y, h0, l0); split2h(v.z, v.w, h1, l1);
        ((uint2*)hi)[i] = make_uint2(h0, h1);
        ((uint2*)lo)[i] = make_uint2(l0, l1);
    }
}
__global__ void round_kernel(const float* __restrict__ in,
                             __half* __restrict__ out, int n4)
{
    int i = blockIdx.x * blockDim.x + threadIdx.x;
    if (i < n4) {
        float4 v = ((const float4*)in)[i];
        ((uint2*)out)[i] = make_uint2(round2h(v.x, v.y), round2h(v.z, v.w));
    }
}

// =====================================================================
// GEMM (fp16 x2): C = A @ B.  A hi/lo fp16 planes, B single fp16.
// 128x128 tile, BK=32, 256 thr, 3-stage cp.async, ldmatrix.
// =====================================================================
#define GSTG 24576
extern __shared__ char dsm[];

__device__ __forceinline__ void gemm_issue(
    uint32_t s0, const __half* Ah, const __half* Al, const __half* B,
    int bm, int bn, int k0, int K, int N, int tid)
{
#pragma unroll
    for (int it = 0; it < 2; it++) {
        int id = tid + it * 256;
        int r = id >> 2, c = id & 3;
        uint32_t d = s0 + r * 64 + ((c ^ ((r >> 1) & 3)) << 4);
        size_t go = (size_t)(bm + r) * K + k0 + c * 8;
        cpa16(d,        Ah + go);
        cpa16(d + 8192, Al + go);
    }
#pragma unroll
    for (int it = 0; it < 2; it++) {
        int id = tid + it * 256;
        int k = id >> 4, c = id & 15;
        uint32_t d = s0 + 16384 + k * 256 + ((c ^ (k & 7)) << 4);
        cpa16(d, B + (size_t)(k0 + k) * N + bn + c * 8);
    }
}

__global__ __launch_bounds__(256, 2) void gemm_h2(
    const __half* __restrict__ Ah, const __half* __restrict__ Al,
    const __half* __restrict__ B,
    float* __restrict__ C, int M, int N, int K, int mode)
{
    const uint32_t sb = (uint32_t)__cvta_generic_to_shared(dsm);
    const int tid = threadIdx.x, lane = tid & 31, wid = tid >> 5;
    const int g = lane >> 2, t = lane & 3;
    const int m8 = lane >> 3, ri = lane & 7;
    const int wm = wid & 3, wn = wid >> 2;
    const int bm = blockIdx.y * 128, bn = blockIdx.x * 128;

    float acc[2][8][4];
#pragma unroll
    for (int mt = 0; mt < 2; mt++)
#pragma unroll
        for (int nt = 0; nt < 8; nt++)
#pragma unroll
            for (int i = 0; i < 4; i++) acc[mt][nt][i] = 0.f;

    const int NCH = K / 32;
    gemm_issue(sb,        Ah, Al, B, bm, bn, 0,  K, N, tid); CP_COMMIT();
    gemm_issue(sb + GSTG, Ah, Al, B, bm, bn, 32, K, N, tid); CP_COMMIT();

    for (int ch = 0; ch < NCH; ch++) {
        if (ch + 2 < NCH)
            gemm_issue(sb + ((ch + 2) % 3) * GSTG, Ah, Al, B,
                       bm, bn, (ch + 2) * 32, K, N, tid);
        CP_COMMIT();
        CP_WAIT(2);
        __syncthreads();

        const uint32_t s0 = sb + (ch % 3) * GSTG;
#pragma unroll
        for (int ks = 0; ks < 2; ks++) {
            unsigned ah[2][4], al[2][4];
#pragma unroll
            for (int mt = 0; mt < 2; mt++) {
                int row = wm * 32 + mt * 16 + (m8 & 1) * 8 + ri;
                int c4  = 2 * ks + (m8 >> 1);
                uint32_t a = s0 + row * 64 + ((c4 ^ ((row >> 1) & 3)) << 4);
                ldsm4(ah[mt][0], ah[mt][1], ah[mt][2], ah[mt][3], a);
                ldsm4(al[mt][0], al[mt][1], al[mt][2], al[mt][3], a + 8192);
            }
#pragma unroll
            for (int ntp = 0; ntp < 4; ntp++) {
                int kr = 16 * ks + (m8 & 1) * 8 + ri;
                int cc = wn * 8 + ntp * 2 + (m8 >> 1);
                uint32_t ba = s0 + 16384 + kr * 256 + ((cc ^ (kr & 7)) << 4);
                unsigned bh[4];
                ldsm4t(bh[0], bh[1], bh[2], bh[3], ba);
                float* c00 = acc[0][ntp * 2 + 0];
                float* c10 = acc[1][ntp * 2 + 0];
                float* c01 = acc[0][ntp * 2 + 1];
                float* c11 = acc[1][ntp * 2 + 1];
                mma16(c00, ah[0], bh[0], bh[1]);
                mma16(c10, ah[1], bh[0], bh[1]);
                mma16(c01, ah[0], bh[2], bh[3]);
                mma16(c11, ah[1], bh[2], bh[3]);
                mma16(c00, al[0], bh[0], bh[1]);
                mma16(c10, al[1], bh[0], bh[1]);
                mma16(c01, al[0], bh[2], bh[3]);
                mma16(c11, al[1], bh[2], bh[3]);
            }
        }
        __syncthreads();
    }

    // ---- epilogue ----
    if (mode == 0) {
#pragma unroll
        for (int mt = 0; mt < 2; mt++) {
#pragma unroll
            for (int nt = 0; nt < 8; nt++) {
                const int row = bm + wm * 32 + mt * 16 + g;
                const int col = bn + wn * 64 + nt * 8 + 2 * t;
                *(float2*)&C[(size_t)row * N + col] =
                    make_float2(acc[mt][nt][0], acc[mt][nt][1]);
                *(float2*)&C[(size_t)(row + 8) * N + col] =
                    make_float2(acc[mt][nt][2], acc[mt][nt][3]);
            }
        }
    } else {
#pragma unroll
        for (int mt = 0; mt < 2; mt++) {
#pragma unroll
            for (int nt = 0; nt < 8; nt++) {
                const int row = bm + wm * 32 + mt * 16 + g;
                const int col = bn + wn * 64 + nt * 8 + 2 * t;
                const int sec = col >> 10, hh = (col >> 6) & 15, d = col & 63;
                const int bb = row >> 11, tok = row & 2047;
                size_t idx = (((size_t)bb * NHEAD + hh) * TQ + tok) * DHEAD + d;
                if (sec == 0) {
                    unsigned hw, lw;
                    split2h(acc[mt][nt][0], acc[mt][nt][1], hw, lw);
                    *(unsigned*)&gQh[idx] = hw; *(unsigned*)&gQl[idx] = lw;
                    split2h(acc[mt][nt][2], acc[mt][nt][3], hw, lw);
                    *(unsigned*)&gQh[idx + 8 * DHEAD] = hw;
                    *(unsigned*)&gQl[idx + 8 * DHEAD] = lw;
                } else {
                    __half* p = (sec == 1) ? gK : gV;
                    *(unsigned*)&p[idx] = round2h(acc[mt][nt][0], acc[mt][nt][1]);
                    *(unsigned*)&p[idx + 8 * DHEAD] = round2h(acc[mt][nt][2], acc[mt][nt][3]);
                }
            }
        }
    }
}

// =====================================================================
// Flash attention: Q hi/lo fp16, K/V single fp16. 64KB smem, occ 2.
// =====================================================================
#define FKV0 32768
#define FSTG 16384

__device__ __forceinline__ void flash_issue_kv(uint32_t s0, size_t base, int j, int tid)
{
#pragma unroll
    for (int it = 0; it < 2; it++) {
        int id = tid + it * 256;
        int r = id >> 3, c = id & 7;
        uint32_t d = s0 + r * 128 + ((c ^ (r & 7)) << 4);
        size_t go = base + (size_t)(j * 64 + r) * DHEAD + c * 8;
        cpa16(d,        gK + go);
        cpa16(d + 8192, gV + go);
    }
}

__global__ __launch_bounds__(256, 2) void flash_h2()
{
    __shared__ float sred[64];
    const uint32_t sb = (uint32_t)__cvta_generic_to_shared(dsm);
    const int qt = (int)gridDim.x - 1 - (int)blockIdx.x;   // longest-first
    const int h = blockIdx.y, b = blockIdx.z;
    const int tid = threadIdx.x, lane = tid & 31, wid = tid >> 5;
    const int g = lane >> 2, t = lane & 3;
    const int m8 = lane >> 3, ri = lane & 7;
    const size_t base = (size_t)(b * NHEAD + h) * TQ * DHEAD;

    // ---- Q hi/lo cp.async: planes at sb (hi) and sb+16384 (lo) ----
#pragma unroll
    for (int it = 0; it < 4; it++) {
        int id = tid + it * 256;
        int r = id >> 3, c = id & 7;
        uint32_t d = sb + r * 128 + ((c ^ (r & 7)) << 4);
        size_t go = base + (size_t)(qt * 128 + r) * DHEAD + c * 8;
        cpa16(d,         gQh + go);
        cpa16(d + 16384, gQl + go);
    }
    CP_COMMIT();
    flash_issue_kv(sb + FKV0, base, 0, tid); CP_COMMIT();
    CP_WAIT(1);
    __syncthreads();

    // ---- hoist Q fragments ----
    unsigned qh[4][4], ql[4][4];
#pragma unroll
    for (int ks = 0; ks < 4; ks++) {
        int row = wid * 16 + (m8 & 1) * 8 + ri;
        int c = 2 * ks + (m8 >> 1);
        uint32_t a = sb + row * 128 + ((c ^ (row & 7)) << 4);
        ldsm4(qh[ks][0], qh[ks][1], qh[ks][2], qh[ks][3], a);
        ldsm4(ql[ks][0], ql[ks][1], ql[ks][2], ql[ks][3], a + 16384);
    }

    float oc[8][4];
#pragma unroll
    for (int nt = 0; nt < 8; nt++)
#pragma unroll
        for (int i = 0; i < 4; i++) oc[nt][i] = 0.f;

    float m0 = -1e30f, m1 = -1e30f, l0s = 0.f, l1s = 0.f, aa0 = 0.f, aa1 = 0.f;
    const int rowbase = qt * 128 + wid * 16;
    const int nj = 2 * qt + 2;

    for (int j = 0; j < nj; j++) {
        if (j + 1 < nj) flash_issue_kv(sb + FKV0 + ((j + 1) & 1) * FSTG, base, j + 1, tid);
        CP_COMMIT();
        CP_WAIT(1);
        __syncthreads();
        const uint32_t kv = sb + FKV0 + (j & 1) * FSTG;

        // ---- S = Q K^T ----
        float sc[8][4];
#pragma unroll
        for (int nt = 0; nt < 8; nt++)
#pragma unroll
            for (int i = 0; i < 4; i++) sc[nt][i] = 0.f;

#pragma unroll
        for (int ks = 0; ks < 4; ks++) {
#pragma unroll
            for (int ntp = 0; ntp < 4; ntp++) {
                int kr = ntp * 16 + (m8 & 1) * 8 + ri;
                int c = 2 * ks + (m8 >> 1);
                uint32_t ka = kv + kr * 128 + ((c ^ (kr & 7)) << 4);
                unsigned kh[4];
                ldsm4(kh[0], kh[1], kh[2], kh[3], ka);
                float* s0p = sc[2 * ntp];
                float* s1p = sc[2 * ntp + 1];
                mma16(s0p, qh[ks], kh[0], kh[2]);
                mma16(s1p, qh[ks], kh[1], kh[3]);
                mma16(s0p, ql[ks], kh[0], kh[2]);
                mma16(s1p, ql[ks], kh[1], kh[3]);
            }
        }

        // ---- scale + causal mask ----
        const bool needmask = (j * 64 + 63) > rowbase;
#pragma unroll
        for (int nt = 0; nt < 8; nt++) {
#pragma unroll
            for (int cc = 0; cc < 4; cc++) {
                float v = sc[nt][cc] * 0.125f;
                if (needmask) {
                    int col = j * 64 + nt * 8 + 2 * t + (cc & 1);
                    int row = rowbase + g + ((cc >> 1) << 3);
                    if (col > row) v = -1e30f;
                }
                sc[nt][cc] = v;
            }
        }

        // ---- online softmax + entropy ----
        float mt0 = -1e30f, mt1 = -1e30f;
#pragma unroll
        for (int nt = 0; nt < 8; nt++) {
            mt0 = fmaxf(mt0, fmaxf(sc[nt][0], sc[nt][1]));
            mt1 = fmaxf(mt1, fmaxf(sc[nt][2], sc[nt][3]));
        }
        mt0 = fmaxf(mt0, __shfl_xor_sync(0xffffffffu, mt0, 1));
        mt0 = fmaxf(mt0, __shfl_xor_sync(0xffffffffu, mt0, 2));
        mt1 = fmaxf(mt1, __shfl_xor_sync(0xffffffffu, mt1, 1));
        mt1 = fmaxf(mt1, __shfl_xor_sync(0xffffffffu, mt1, 2));

        const float mn0 = fmaxf(m0, mt0), mn1 = fmaxf(m1, mt1);
        const float ex0 = __expf(m0 - mn0), ex1 = __expf(m1 - mn1);

        float ls0 = 0.f, ls1 = 0.f, as0 = 0.f, as1 = 0.f;
#pragma unroll
        for (int nt = 0; nt < 8; nt++) {
            float s0 = sc[nt][0], s1 = sc[nt][1];
            float s2 = sc[nt][2], s3 = sc[nt][3];
            float p0 = __expf(s0 - mn0), p1 = __expf(s1 - mn0);
            float p2 = __expf(s2 - mn1), p3 = __expf(s3 - mn1);
            sc[nt][0] = p0; sc[nt][1] = p1; sc[nt][2] = p2; sc[nt][3] = p3;
            ls0 += p0 + p1;           ls1 += p2 + p3;
            as0 += p0 * s0 + p1 * s1; as1 += p2 * s2 + p3 * s3;
        }
        ls0 += __shfl_xor_sync(0xffffffffu, ls0, 1);
        ls0 += __shfl_xor_sync(0xffffffffu, ls0, 2);
        ls1 += __shfl_xor_sync(0xffffffffu, ls1, 1);
        ls1 += __shfl_xor_sync(0xffffffffu, ls1, 2);
        as0 += __shfl_xor_sync(0xffffffffu, as0, 1);
        as0 += __shfl_xor_sync(0xffffffffu, as0, 2);
        as1 += __shfl_xor_sync(0xffffffffu, as1, 1);
        as1 += __shfl_xor_sync(0xffffffffu, as1, 2);

        l0s = l0s * ex0 + ls0;  aa0 = aa0 * ex0 + as0;  m0 = mn0;
        l1s = l1s * ex1 + ls1;  aa1 = aa1 * ex1 + as1;  m1 = mn1;

#pragma unroll
        for (int nt = 0; nt < 8; nt++) {
            oc[nt][0] *= ex0; oc[nt][1] *= ex0;
            oc[nt][2] *= ex1; oc[nt][3] *= ex1;
        }

        // ---- pack P to fp16 hi/lo ----
        unsigned ph0[8], pl0[8], ph1[8], pl1[8];
#pragma unroll
        for (int nt = 0; nt < 8; nt++) {
            split2h(sc[nt][0], sc[nt][1], ph0[nt], pl0[nt]);
            split2h(sc[nt][2], sc[nt][3], ph1[nt], pl1[nt]);
        }

        // ---- O += P @ V ----
#pragma unroll
        for (int ks = 0; ks < 4; ks++) {
            unsigned aH[4] = {ph0[2*ks], ph1[2*ks], ph0[2*ks+1], ph1[2*ks+1]};
            unsigned aL[4] = {pl0[2*ks], pl1[2*ks], pl0[2*ks+1], pl1[2*ks+1]};
#pragma unroll
            for (int ntp = 0; ntp < 4; ntp++) {
                int vr = 16 * ks + (m8 & 1) * 8 + ri;
                int c = ntp * 2 + (m8 >> 1);
                uint32_t va = kv + 8192 + vr * 128 + ((c ^ (vr & 7)) << 4);
                unsigned vh[4];
                ldsm4t(vh[0], vh[1], vh[2], vh[3], va);
                float* o0 = oc[2 * ntp];
                float* o1 = oc[2 * ntp + 1];
                mma16(o0, aH, vh[0], vh[1]);
                mma16(o1, aH, vh[2], vh[3]);
                mma16(o0, aL, vh[0], vh[1]);
                mma16(o1, aL, vh[2], vh[3]);
            }
        }
        __syncthreads();
    }

    // ---- epilogue: write yatt hi/lo planes ----
    const float inv0 = 1.f / l0s, inv1 = 1.f / l1s;
    const int trow = rowbase + g;
#pragma unroll
    for (int nt = 0; nt < 8; nt++) {
        const int col = h * DHEAD + nt * 8 + 2 * t;
        size_t idx = ((size_t)b * TQ + trow) * CDIM + col;
        unsigned hw, lw;
        split2h(oc[nt][0] * inv0, oc[nt][1] * inv0, hw, lw);
        *(unsigned*)&gYh[idx] = hw; *(unsigned*)&gYl[idx] = lw;
        split2h(oc[nt][2] * inv1, oc[nt][3] * inv1, hw, lw);
        *(unsigned*)&gYh[idx + 8 * CDIM] = hw; *(unsigned*)&gYl[idx + 8 * CDIM] = lw;
    }

    // ---- entropy partial ----
    if (t == 0) {
        float H = (m0 + __logf(l0s) - aa0 / l0s) + (m1 + __logf(l1s) - aa1 / l1s);
        sred[wid * 8 + g] = H;
    }
    __syncthreads();
    if (tid == 0) {
        float s = 0.f;
#pragma unroll 8
        for (int r = 0; r < 64; r++) s += sred[r];
        g_ent[((size_t)b * NHEAD + h) * NQT2 + qt] = s;
    }
}

// =====================================================================
// entropy final reduction
// =====================================================================
__global__ void ent_final_kernel(float* __restrict__ out, int out_size)
{
    __shared__ float red[256];
    int tid = threadIdx.x;
    float s = 0.f;
    for (int i = tid; i < BATCH * NHEAD * NQT2; i += 256) s += g_ent[i];
    red[tid] = s;
    __syncthreads();
    for (int st = 128; st > 0; st >>= 1) {
        if (tid < st) red[tid] += red[tid + st];
        __syncthreads();
    }
    if (tid == 0) out[out_size - 1] = red[0] / (float)NROWS;
}

// =====================================================================
// launch
// =====================================================================
extern "C" void kernel_launch(void* const* d_in, const int* in_sizes, int n_in,
                              void* d_out, int out_size)
{
    const float* x      = (const float*)d_in[0];
    const float* w_attn = (const float*)d_in[1];
    const float* w_proj = (const float*)d_in[2];
    float* out = (float*)d_out;
    (void)in_sizes; (void)n_in;

    __half *xh, *xl, *wa, *wp, *yh, *yl;
    cudaGetSymbolAddress((void**)&xh, gXh); cudaGetSymbolAddress((void**)&xl, gXl);
    cudaGetSymbolAddress((void**)&wa, gWA); cudaGetSymbolAddress((void**)&wp, gWP);
    cudaGetSymbolAddress((void**)&yh, gYh); cudaGetSymbolAddress((void**)&yl, gYl);

    const int GEMM_SMEM  = 3 * GSTG;           // 73728
    const int FLASH_SMEM = FKV0 + 2 * FSTG;    // 65536
    cudaFuncSetAttribute(gemm_h2,
                         cudaFuncAttributeMaxDynamicSharedMemorySize, GEMM_SMEM);
    cudaFuncSetAttribute(flash_h2,
                         cudaFuncAttributeMaxDynamicSharedMemorySize, FLASH_SMEM);

    // 0) prep: x -> hi/lo, weights -> fp16
    {
        int n4x = BATCH * TQ * CDIM / 4;
        split_kernel<<<(n4x + 255) / 256, 256>>>(x, xh, xl, n4x);
        int n4a = CDIM * C3 / 4;
        round_kernel<<<(n4a + 255) / 256, 256>>>(w_attn, wa, n4a);
        int n4p = CDIM * CDIM / 4;
        round_kernel<<<(n4p + 255) / 256, 256>>>(w_proj, wp, n4p);
    }
    // 1) qkv = x @ w_attn -> Q hi/lo, K, V (mode 1)
    {
        dim3 grid(C3 / 128, (BATCH * TQ) / 128);
        gemm_h2<<<grid, 256, GEMM_SMEM>>>(xh, xl, wa, nullptr,
                                          BATCH * TQ, C3, CDIM, 1);
    }
    // 2) flash attention + entropy partials -> gY planes
    {
        dim3 grid(NQT2, NHEAD, BATCH);
        flash_h2<<<grid, 256, FLASH_SMEM>>>();
    }
    // 3) y = yatt @ w_proj -> d_out (mode 0)
    {
        dim3 grid(CDIM / 128, (BATCH * TQ) / 128);
        gemm_h2<<<grid, 256, GEMM_SMEM>>>(yh, yl, wp, out,
                                          BATCH * TQ, CDIM, CDIM, 0);
    }
    // 4) entropy scalar
    ent_final_kernel<<<1, 256>>>(out, out_size);
}

// round 9
// speedup vs baseline: 2.2566x; 1.6193x over previous
#include <cuda_runtime.h>
#include <cuda_fp16.h>
#include <stdint.h>

// ---------------- problem constants ----------------
#define BATCH  2
#define TQ     2048
#define CDIM   1024
#define NHEAD  16
#define DHEAD  64
#define C3     (3 * CDIM)
#define NQT2   (TQ / 128)
#define NROWS  (BATCH * NHEAD * TQ)
#define QKVN   (BATCH * NHEAD * TQ * DHEAD)

// ---------------- fp16 planes (device scratch) ----------------
__device__ __align__(16) __half gX[BATCH*TQ*CDIM];
__device__ __align__(16) __half gWA[CDIM*C3];
__device__ __align__(16) __half gWP[CDIM*CDIM];
__device__ __align__(16) __half gQ[QKVN];
__device__ __align__(16) __half gK[QKVN];
__device__ __align__(16) __half gV[QKVN];
__device__ __align__(16) __half gY[BATCH*TQ*CDIM];
__device__ float g_ent[BATCH * NHEAD * NQT2];

// ---------------- helpers ----------------
__device__ __forceinline__ unsigned round2h(float a, float b) {
    __half2 h = __floats2half2_rn(a, b);
    return *reinterpret_cast<unsigned*>(&h);
}
// fp16 m16n8k16 mma, fp32 accumulate (non-volatile)
__device__ __forceinline__ void mma16(float* c, const unsigned* a, unsigned b0, unsigned b1) {
    asm("mma.sync.aligned.m16n8k16.row.col.f32.f16.f16.f32 "
        "{%0,%1,%2,%3},{%4,%5,%6,%7},{%8,%9},{%0,%1,%2,%3};"
        : "+f"(c[0]), "+f"(c[1]), "+f"(c[2]), "+f"(c[3])
        : "r"(a[0]), "r"(a[1]), "r"(a[2]), "r"(a[3]), "r"(b0), "r"(b1));
}
__device__ __forceinline__ void ldsm4(unsigned& r0, unsigned& r1, unsigned& r2, unsigned& r3, uint32_t a) {
    asm volatile("ldmatrix.sync.aligned.m8n8.x4.shared.b16 {%0,%1,%2,%3},[%4];"
        : "=r"(r0), "=r"(r1), "=r"(r2), "=r"(r3) : "r"(a));
}
__device__ __forceinline__ void ldsm4t(unsigned& r0, unsigned& r1, unsigned& r2, unsigned& r3, uint32_t a) {
    asm volatile("ldmatrix.sync.aligned.m8n8.x4.trans.shared.b16 {%0,%1,%2,%3},[%4];"
        : "=r"(r0), "=r"(r1), "=r"(r2), "=r"(r3) : "r"(a));
}
__device__ __forceinline__ void cpa16(uint32_t d, const void* s) {
    asm volatile("cp.async.ca.shared.global [%0],[%1],16;" :: "r"(d), "l"(s));
}
#define CP_COMMIT() asm volatile("cp.async.commit_group;" ::: "memory")
#define CP_WAIT(N)  asm volatile("cp.async.wait_group %0;" :: "n"(N) : "memory")

// =====================================================================
// prep: fp32 -> fp16
// =====================================================================
__global__ void round_kernel(const float* __restrict__ in,
                             __half* __restrict__ out, int n4)
{
    int i = blockIdx.x * blockDim.x + threadIdx.x;
    if (i < n4) {
        float4 v = ((const float4*)in)[i];
        ((uint2*)out)[i] = make_uint2(round2h(v.x, v.y), round2h(v.z, v.w));
    }
}

// =====================================================================
// GEMM (fp16 single-pass): C = A @ B. 128x128 tile, BK=32, 256 thr,
// 3-stage cp.async, ldmatrix. A at s0 (8KB), B at s0+8192 (8KB).
// =====================================================================
#define GSTG 16384
extern __shared__ char dsm[];

__device__ __forceinline__ void gemm_issue(
    uint32_t s0, const __half* A, const __half* B,
    int bm, int bn, int k0, int K, int N, int tid)
{
#pragma unroll
    for (int it = 0; it < 2; it++) {
        int id = tid + it * 256;
        int r = id >> 2, c = id & 3;
        uint32_t d = s0 + r * 64 + ((c ^ ((r >> 1) & 3)) << 4);
        cpa16(d, A + (size_t)(bm + r) * K + k0 + c * 8);
    }
#pragma unroll
    for (int it = 0; it < 2; it++) {
        int id = tid + it * 256;
        int k = id >> 4, c = id & 15;
        uint32_t d = s0 + 8192 + k * 256 + ((c ^ (k & 7)) << 4);
        cpa16(d, B + (size_t)(k0 + k) * N + bn + c * 8);
    }
}

__global__ __launch_bounds__(256, 2) void gemm_h1(
    const __half* __restrict__ A, const __half* __restrict__ B,
    float* __restrict__ C, int M, int N, int K, int mode)
{
    const uint32_t sb = (uint32_t)__cvta_generic_to_shared(dsm);
    const int tid = threadIdx.x, lane = tid & 31, wid = tid >> 5;
    const int g = lane >> 2, t = lane & 3;
    const int m8 = lane >> 3, ri = lane & 7;
    const int wm = wid & 3, wn = wid >> 2;
    const int bm = blockIdx.y * 128, bn = blockIdx.x * 128;

    float acc[2][8][4];
#pragma unroll
    for (int mt = 0; mt < 2; mt++)
#pragma unroll
        for (int nt = 0; nt < 8; nt++)
#pragma unroll
            for (int i = 0; i < 4; i++) acc[mt][nt][i] = 0.f;

    const int NCH = K / 32;
    gemm_issue(sb,        A, B, bm, bn, 0,  K, N, tid); CP_COMMIT();
    gemm_issue(sb + GSTG, A, B, bm, bn, 32, K, N, tid); CP_COMMIT();

    for (int ch = 0; ch < NCH; ch++) {
        if (ch + 2 < NCH)
            gemm_issue(sb + ((ch + 2) % 3) * GSTG, A, B,
                       bm, bn, (ch + 2) * 32, K, N, tid);
        CP_COMMIT();
        CP_WAIT(2);
        __syncthreads();

        const uint32_t s0 = sb + (ch % 3) * GSTG;
#pragma unroll
        for (int ks = 0; ks < 2; ks++) {
            unsigned ah[2][4];
#pragma unroll
            for (int mt = 0; mt < 2; mt++) {
                int row = wm * 32 + mt * 16 + (m8 & 1) * 8 + ri;
                int c4  = 2 * ks + (m8 >> 1);
                uint32_t a = s0 + row * 64 + ((c4 ^ ((row >> 1) & 3)) << 4);
                ldsm4(ah[mt][0], ah[mt][1], ah[mt][2], ah[mt][3], a);
            }
#pragma unroll
            for (int ntp = 0; ntp < 4; ntp++) {
                int kr = 16 * ks + (m8 & 1) * 8 + ri;
                int cc = wn * 8 + ntp * 2 + (m8 >> 1);
                uint32_t ba = s0 + 8192 + kr * 256 + ((cc ^ (kr & 7)) << 4);
                unsigned bh[4];
                ldsm4t(bh[0], bh[1], bh[2], bh[3], ba);
                mma16(acc[0][ntp * 2 + 0], ah[0], bh[0], bh[1]);
                mma16(acc[1][ntp * 2 + 0], ah[1], bh[0], bh[1]);
                mma16(acc[0][ntp * 2 + 1], ah[0], bh[2], bh[3]);
                mma16(acc[1][ntp * 2 + 1], ah[1], bh[2], bh[3]);
            }
        }
        __syncthreads();
    }

    // ---- epilogue ----
    if (mode == 0) {
#pragma unroll
        for (int mt = 0; mt < 2; mt++) {
#pragma unroll
            for (int nt = 0; nt < 8; nt++) {
                const int row = bm + wm * 32 + mt * 16 + g;
                const int col = bn + wn * 64 + nt * 8 + 2 * t;
                *(float2*)&C[(size_t)row * N + col] =
                    make_float2(acc[mt][nt][0], acc[mt][nt][1]);
                *(float2*)&C[(size_t)(row + 8) * N + col] =
                    make_float2(acc[mt][nt][2], acc[mt][nt][3]);
            }
        }
    } else {
#pragma unroll
        for (int mt = 0; mt < 2; mt++) {
#pragma unroll
            for (int nt = 0; nt < 8; nt++) {
                const int row = bm + wm * 32 + mt * 16 + g;
                const int col = bn + wn * 64 + nt * 8 + 2 * t;
                const int sec = col >> 10, hh = (col >> 6) & 15, d = col & 63;
                const int bb = row >> 11, tok = row & 2047;
                size_t idx = (((size_t)bb * NHEAD + hh) * TQ + tok) * DHEAD + d;
                __half* p = (sec == 0) ? gQ : ((sec == 1) ? gK : gV);
                *(unsigned*)&p[idx] = round2h(acc[mt][nt][0], acc[mt][nt][1]);
                *(unsigned*)&p[idx + 8 * DHEAD] = round2h(acc[mt][nt][2], acc[mt][nt][3]);
            }
        }
    }
}

// =====================================================================
// Flash attention: all fp16 single-pass. 48KB smem, occ 2.
// Q 16KB at sb; KV stages 16KB each at sb+16384.
// =====================================================================
#define FKV0 16384
#define FSTG 16384

__device__ __forceinline__ void flash_issue_kv(uint32_t s0, size_t base, int j, int tid)
{
#pragma unroll
    for (int it = 0; it < 2; it++) {
        int id = tid + it * 256;
        int r = id >> 3, c = id & 7;
        uint32_t d = s0 + r * 128 + ((c ^ (r & 7)) << 4);
        size_t go = base + (size_t)(j * 64 + r) * DHEAD + c * 8;
        cpa16(d,        gK + go);
        cpa16(d + 8192, gV + go);
    }
}

__global__ __launch_bounds__(256, 2) void flash_h1()
{
    __shared__ float sred[64];
    const uint32_t sb = (uint32_t)__cvta_generic_to_shared(dsm);
    const int qt = (int)gridDim.x - 1 - (int)blockIdx.x;   // longest-first
    const int h = blockIdx.y, b = blockIdx.z;
    const int tid = threadIdx.x, lane = tid & 31, wid = tid >> 5;
    const int g = lane >> 2, t = lane & 3;
    const int m8 = lane >> 3, ri = lane & 7;
    const size_t base = (size_t)(b * NHEAD + h) * TQ * DHEAD;

    // ---- Q cp.async ----
#pragma unroll
    for (int it = 0; it < 2; it++) {
        int id = tid + it * 256;
        int r = id >> 2, c = id & 3;
        // 128 rows x 128B, 4 chunks per row handled by (id>>2, id&3)? rows=128 needs 512 ids
        uint32_t d = sb + r * 128 + (((c * 2) ^ (r & 7)) << 4);
        (void)d;
    }
    // proper Q load: 1024 16B chunks? Q = 128 rows x 64 fp16 = 16KB = 1024 chunks
#pragma unroll
    for (int it = 0; it < 4; it++) {
        int id = tid + it * 256;
        int r = id >> 3, c = id & 7;
        uint32_t d = sb + r * 128 + ((c ^ (r & 7)) << 4);
        cpa16(d, gQ + base + (size_t)(qt * 128 + r) * DHEAD + c * 8);
    }
    CP_COMMIT();
    flash_issue_kv(sb + FKV0, base, 0, tid); CP_COMMIT();
    CP_WAIT(1);
    __syncthreads();

    // ---- hoist Q fragments ----
    unsigned qh[4][4];
#pragma unroll
    for (int ks = 0; ks < 4; ks++) {
        int row = wid * 16 + (m8 & 1) * 8 + ri;
        int c = 2 * ks + (m8 >> 1);
        uint32_t a = sb + row * 128 + ((c ^ (row & 7)) << 4);
        ldsm4(qh[ks][0], qh[ks][1], qh[ks][2], qh[ks][3], a);
    }

    float oc[8][4];
#pragma unroll
    for (int nt = 0; nt < 8; nt++)
#pragma unroll
        for (int i = 0; i < 4; i++) oc[nt][i] = 0.f;

    float m0 = -1e30f, m1 = -1e30f, l0s = 0.f, l1s = 0.f, aa0 = 0.f, aa1 = 0.f;
    const int rowbase = qt * 128 + wid * 16;
    const int nj = 2 * qt + 2;

    for (int j = 0; j < nj; j++) {
        if (j + 1 < nj) flash_issue_kv(sb + FKV0 + ((j + 1) & 1) * FSTG, base, j + 1, tid);
        CP_COMMIT();
        CP_WAIT(1);
        __syncthreads();
        const uint32_t kv = sb + FKV0 + (j & 1) * FSTG;

        // ---- S = Q K^T ----
        float sc[8][4];
#pragma unroll
        for (int nt = 0; nt < 8; nt++)
#pragma unroll
            for (int i = 0; i < 4; i++) sc[nt][i] = 0.f;

#pragma unroll
        for (int ks = 0; ks < 4; ks++) {
#pragma unroll
            for (int ntp = 0; ntp < 4; ntp++) {
                int kr = ntp * 16 + (m8 & 1) * 8 + ri;
                int c = 2 * ks + (m8 >> 1);
                uint32_t ka = kv + kr * 128 + ((c ^ (kr & 7)) << 4);
                unsigned kh[4];
                ldsm4(kh[0], kh[1], kh[2], kh[3], ka);
                mma16(sc[2 * ntp],     qh[ks], kh[0], kh[2]);
                mma16(sc[2 * ntp + 1], qh[ks], kh[1], kh[3]);
            }
        }

        // ---- scale + causal mask ----
        const bool needmask = (j * 64 + 63) > rowbase;
#pragma unroll
        for (int nt = 0; nt < 8; nt++) {
#pragma unroll
            for (int cc = 0; cc < 4; cc++) {
                float v = sc[nt][cc] * 0.125f;
                if (needmask) {
                    int col = j * 64 + nt * 8 + 2 * t + (cc & 1);
                    int row = rowbase + g + ((cc >> 1) << 3);
                    if (col > row) v = -1e30f;
                }
                sc[nt][cc] = v;
            }
        }

        // ---- online softmax + entropy ----
        float mt0 = -1e30f, mt1 = -1e30f;
#pragma unroll
        for (int nt = 0; nt < 8; nt++) {
            mt0 = fmaxf(mt0, fmaxf(sc[nt][0], sc[nt][1]));
            mt1 = fmaxf(mt1, fmaxf(sc[nt][2], sc[nt][3]));
        }
        mt0 = fmaxf(mt0, __shfl_xor_sync(0xffffffffu, mt0, 1));
        mt0 = fmaxf(mt0, __shfl_xor_sync(0xffffffffu, mt0, 2));
        mt1 = fmaxf(mt1, __shfl_xor_sync(0xffffffffu, mt1, 1));
        mt1 = fmaxf(mt1, __shfl_xor_sync(0xffffffffu, mt1, 2));

        const float mn0 = fmaxf(m0, mt0), mn1 = fmaxf(m1, mt1);
        const float ex0 = __expf(m0 - mn0), ex1 = __expf(m1 - mn1);

        float ls0 = 0.f, ls1 = 0.f, as0 = 0.f, as1 = 0.f;
#pragma unroll
        for (int nt = 0; nt < 8; nt++) {
            float s0 = sc[nt][0], s1 = sc[nt][1];
            float s2 = sc[nt][2], s3 = sc[nt][3];
            float p0 = __expf(s0 - mn0), p1 = __expf(s1 - mn0);
            float p2 = __expf(s2 - mn1), p3 = __expf(s3 - mn1);
            sc[nt][0] = p0; sc[nt][1] = p1; sc[nt][2] = p2; sc[nt][3] = p3;
            ls0 += p0 + p1;           ls1 += p2 + p3;
            as0 += p0 * s0 + p1 * s1; as1 += p2 * s2 + p3 * s3;
        }
        ls0 += __shfl_xor_sync(0xffffffffu, ls0, 1);
        ls0 += __shfl_xor_sync(0xffffffffu, ls0, 2);
        ls1 += __shfl_xor_sync(0xffffffffu, ls1, 1);
        ls1 += __shfl_xor_sync(0xffffffffu, ls1, 2);
        as0 += __shfl_xor_sync(0xffffffffu, as0, 1);
        as0 += __shfl_xor_sync(0xffffffffu, as0, 2);
        as1 += __shfl_xor_sync(0xffffffffu, as1, 1);
        as1 += __shfl_xor_sync(0xffffffffu, as1, 2);

        l0s = l0s * ex0 + ls0;  aa0 = aa0 * ex0 + as0;  m0 = mn0;
        l1s = l1s * ex1 + ls1;  aa1 = aa1 * ex1 + as1;  m1 = mn1;

#pragma unroll
        for (int nt = 0; nt < 8; nt++) {
            oc[nt][0] *= ex0; oc[nt][1] *= ex0;
            oc[nt][2] *= ex1; oc[nt][3] *= ex1;
        }

        // ---- pack P to fp16 (single) ----
        unsigned ph0[8], ph1[8];
#pragma unroll
        for (int nt = 0; nt < 8; nt++) {
            ph0[nt] = round2h(sc[nt][0], sc[nt][1]);
            ph1[nt] = round2h(sc[nt][2], sc[nt][3]);
        }

        // ---- O += P @ V ----
#pragma unroll
        for (int ks = 0; ks < 4; ks++) {
            unsigned aH[4] = {ph0[2*ks], ph1[2*ks], ph0[2*ks+1], ph1[2*ks+1]};
#pragma unroll
            for (int ntp = 0; ntp < 4; ntp++) {
                int vr = 16 * ks + (m8 & 1) * 8 + ri;
                int c = ntp * 2 + (m8 >> 1);
                uint32_t va = kv + 8192 + vr * 128 + ((c ^ (vr & 7)) << 4);
                unsigned vh[4];
                ldsm4t(vh[0], vh[1], vh[2], vh[3], va);
                mma16(oc[2 * ntp],     aH, vh[0], vh[1]);
                mma16(oc[2 * ntp + 1], aH, vh[2], vh[3]);
            }
        }
        __syncthreads();
    }

    // ---- epilogue: write yatt fp16 ----
    const float inv0 = 1.f / l0s, inv1 = 1.f / l1s;
    const int trow = rowbase + g;
#pragma unroll
    for (int nt = 0; nt < 8; nt++) {
        const int col = h * DHEAD + nt * 8 + 2 * t;
        size_t idx = ((size_t)b * TQ + trow) * CDIM + col;
        *(unsigned*)&gY[idx] = round2h(oc[nt][0] * inv0, oc[nt][1] * inv0);
        *(unsigned*)&gY[idx + 8 * CDIM] = round2h(oc[nt][2] * inv1, oc[nt][3] * inv1);
    }

    // ---- entropy partial ----
    if (t == 0) {
        float H = (m0 + __logf(l0s) - aa0 / l0s) + (m1 + __logf(l1s) - aa1 / l1s);
        sred[wid * 8 + g] = H;
    }
    __syncthreads();
    if (tid == 0) {
        float s = 0.f;
#pragma unroll 8
        for (int r = 0; r < 64; r++) s += sred[r];
        g_ent[((size_t)b * NHEAD + h) * NQT2 + qt] = s;
    }
}

// =====================================================================
// entropy final reduction
// =====================================================================
__global__ void ent_final_kernel(float* __restrict__ out, int out_size)
{
    __shared__ float red[256];
    int tid = threadIdx.x;
    float s = 0.f;
    for (int i = tid; i < BATCH * NHEAD * NQT2; i += 256) s += g_ent[i];
    red[tid] = s;
    __syncthreads();
    for (int st = 128; st > 0; st >>= 1) {
        if (tid < st) red[tid] += red[tid + st];
        __syncthreads();
    }
    if (tid == 0) out[out_size - 1] = red[0] / (float)NROWS;
}

// =====================================================================
// launch
// =====================================================================
extern "C" void kernel_launch(void* const* d_in, const int* in_sizes, int n_in,
                              void* d_out, int out_size)
{
    const float* x      = (const float*)d_in[0];
    const float* w_attn = (const float*)d_in[1];
    const float* w_proj = (const float*)d_in[2];
    float* out = (float*)d_out;
    (void)in_sizes; (void)n_in;

    __half *xp, *wa, *wp, *yp;
    cudaGetSymbolAddress((void**)&xp, gX);
    cudaGetSymbolAddress((void**)&wa, gWA);
    cudaGetSymbolAddress((void**)&wp, gWP);
    cudaGetSymbolAddress((void**)&yp, gY);

    const int GEMM_SMEM  = 3 * GSTG;           // 49152
    const int FLASH_SMEM = FKV0 + 2 * FSTG;    // 49152
    cudaFuncSetAttribute(gemm_h1,
                         cudaFuncAttributeMaxDynamicSharedMemorySize, GEMM_SMEM);
    cudaFuncSetAttribute(flash_h1,
                         cudaFuncAttributeMaxDynamicSharedMemorySize, FLASH_SMEM);

    // 0) prep: round inputs to fp16
    {
        int n4x = BATCH * TQ * CDIM / 4;
        round_kernel<<<(n4x + 255) / 256, 256>>>(x, xp, n4x);
        int n4a = CDIM * C3 / 4;
        round_kernel<<<(n4a + 255) / 256, 256>>>(w_attn, wa, n4a);
        int n4p = CDIM * CDIM / 4;
        round_kernel<<<(n4p + 255) / 256, 256>>>(w_proj, wp, n4p);
    }
    // 1) qkv = x @ w_attn -> Q, K, V fp16 (mode 1)
    {
        dim3 grid(C3 / 128, (BATCH * TQ) / 128);
        gemm_h1<<<grid, 256, GEMM_SMEM>>>(xp, wa, nullptr,
                                          BATCH * TQ, C3, CDIM, 1);
    }
    // 2) flash attention + entropy partials -> gY
    {
        dim3 grid(NQT2, NHEAD, BATCH);
        flash_h1<<<grid, 256, FLASH_SMEM>>>();
    }
    // 3) y = yatt @ w_proj -> d_out (mode 0)
    {
        dim3 grid(CDIM / 128, (BATCH * TQ) / 128);
        gemm_h1<<<grid, 256, GEMM_SMEM>>>(yp, wp, out,
                                          BATCH * TQ, CDIM, CDIM, 0);
    }
    // 4) entropy scalar
    ent_final_kernel<<<1, 256>>>(out, out_size);
}

// round 10
// speedup vs baseline: 2.3757x; 1.0527x over previous
#include <cuda_runtime.h>
#include <cuda_fp16.h>
#include <stdint.h>

// ---------------- problem constants ----------------
#define BATCH  2
#define TQ     2048
#define CDIM   1024
#define NHEAD  16
#define DHEAD  64
#define C3     (3 * CDIM)
#define NQT2   (TQ / 128)
#define NROWS  (BATCH * NHEAD * TQ)
#define QKVN   (BATCH * NHEAD * TQ * DHEAD)
#define LN2F   0.6931471805599453f
#define SC2F   0.1803368801111601f   // 0.125 * log2(e)

// ---------------- fp16 planes (device scratch) ----------------
__device__ __align__(16) __half gX[BATCH*TQ*CDIM];
__device__ __align__(16) __half gWA[CDIM*C3];
__device__ __align__(16) __half gWP[CDIM*CDIM];
__device__ __align__(16) __half gQ[QKVN];
__device__ __align__(16) __half gK[QKVN];
__device__ __align__(16) __half gV[QKVN];
__device__ __align__(16) __half gY[BATCH*TQ*CDIM];
__device__ float g_ent[BATCH * NHEAD * NQT2];

// ---------------- helpers ----------------
__device__ __forceinline__ unsigned round2h(float a, float b) {
    __half2 h = __floats2half2_rn(a, b);
    return *reinterpret_cast<unsigned*>(&h);
}
__device__ __forceinline__ float ex2f(float x) {
    float r; asm("ex2.approx.f32 %0, %1;" : "=f"(r) : "f"(x)); return r;
}
__device__ __forceinline__ unsigned ex2h2(unsigned x) {
    unsigned r; asm("ex2.approx.f16x2 %0, %1;" : "=r"(r) : "r"(x)); return r;
}
// fp16 m16n8k16 mma, fp32 accumulate (non-volatile)
__device__ __forceinline__ void mma16(float* c, const unsigned* a, unsigned b0, unsigned b1) {
    asm("mma.sync.aligned.m16n8k16.row.col.f32.f16.f16.f32 "
        "{%0,%1,%2,%3},{%4,%5,%6,%7},{%8,%9},{%0,%1,%2,%3};"
        : "+f"(c[0]), "+f"(c[1]), "+f"(c[2]), "+f"(c[3])
        : "r"(a[0]), "r"(a[1]), "r"(a[2]), "r"(a[3]), "r"(b0), "r"(b1));
}
__device__ __forceinline__ void ldsm4(unsigned& r0, unsigned& r1, unsigned& r2, unsigned& r3, uint32_t a) {
    asm volatile("ldmatrix.sync.aligned.m8n8.x4.shared.b16 {%0,%1,%2,%3},[%4];"
        : "=r"(r0), "=r"(r1), "=r"(r2), "=r"(r3) : "r"(a));
}
__device__ __forceinline__ void ldsm4t(unsigned& r0, unsigned& r1, unsigned& r2, unsigned& r3, uint32_t a) {
    asm volatile("ldmatrix.sync.aligned.m8n8.x4.trans.shared.b16 {%0,%1,%2,%3},[%4];"
        : "=r"(r0), "=r"(r1), "=r"(r2), "=r"(r3) : "r"(a));
}
__device__ __forceinline__ void cpa16(uint32_t d, const void* s) {
    asm volatile("cp.async.ca.shared.global [%0],[%1],16;" :: "r"(d), "l"(s));
}
#define CP_COMMIT() asm volatile("cp.async.commit_group;" ::: "memory")
#define CP_WAIT(N)  asm volatile("cp.async.wait_group %0;" :: "n"(N) : "memory")

// =====================================================================
// fused prep: round x, w_attn, w_proj to fp16 in ONE launch
// =====================================================================
#define NX4 (BATCH * TQ * CDIM / 4)   // 1,048,576
#define NA4 (CDIM * C3 / 4)           //   786,432
#define NP4 (CDIM * CDIM / 4)         //   262,144
__global__ void prep_kernel(const float* __restrict__ x,
                            const float* __restrict__ wa,
                            const float* __restrict__ wp)
{
    int i = blockIdx.x * blockDim.x + threadIdx.x;
    const float* in; __half* out; int j;
    if (i < NX4)              { in = x;  out = gX;  j = i; }
    else if (i < NX4 + NA4)   { in = wa; out = gWA; j = i - NX4; }
    else if (i < NX4+NA4+NP4) { in = wp; out = gWP; j = i - NX4 - NA4; }
    else return;
    float4 v = ((const float4*)in)[j];
    ((uint2*)out)[j] = make_uint2(round2h(v.x, v.y), round2h(v.z, v.w));
}

// =====================================================================
// GEMM (fp16): C = A @ B. 128x128 tile, BK=32, 256 thr, 3-stage cp.async.
// mode 0: fp32 C (+ block(0,0) computes entropy scalar); mode 1: qkv scatter.
// =====================================================================
#define GSTG 16384
extern __shared__ char dsm[];

__device__ __forceinline__ void gemm_issue(
    uint32_t s0, const __half* A, const __half* B,
    int bm, int bn, int k0, int K, int N, int tid)
{
#pragma unroll
    for (int it = 0; it < 2; it++) {
        int id = tid + it * 256;
        int r = id >> 2, c = id & 3;
        uint32_t d = s0 + r * 64 + ((c ^ ((r >> 1) & 3)) << 4);
        cpa16(d, A + (size_t)(bm + r) * K + k0 + c * 8);
    }
#pragma unroll
    for (int it = 0; it < 2; it++) {
        int id = tid + it * 256;
        int k = id >> 4, c = id & 15;
        uint32_t d = s0 + 8192 + k * 256 + ((c ^ (k & 7)) << 4);
        cpa16(d, B + (size_t)(k0 + k) * N + bn + c * 8);
    }
}

__global__ __launch_bounds__(256, 2) void gemm_h1(
    const __half* __restrict__ A, const __half* __restrict__ B,
    float* __restrict__ C, int M, int N, int K, int mode, int out_size)
{
    const uint32_t sb = (uint32_t)__cvta_generic_to_shared(dsm);
    const int tid = threadIdx.x, lane = tid & 31, wid = tid >> 5;
    const int g = lane >> 2, t = lane & 3;
    const int m8 = lane >> 3, ri = lane & 7;
    const int wm = wid & 3, wn = wid >> 2;
    const int bm = blockIdx.y * 128, bn = blockIdx.x * 128;

    // ---- fused entropy scalar (proj launch only, one block) ----
    if (mode == 0 && blockIdx.x == 0 && blockIdx.y == 0) {
        __shared__ float red[256];
        float s = 0.f;
        for (int i = tid; i < BATCH * NHEAD * NQT2; i += 256) s += g_ent[i];
        red[tid] = s;
        __syncthreads();
        for (int st = 128; st > 0; st >>= 1) {
            if (tid < st) red[tid] += red[tid + st];
            __syncthreads();
        }
        if (tid == 0) C[out_size - 1] = red[0] / (float)NROWS;
    }

    float acc[2][8][4];
#pragma unroll
    for (int mt = 0; mt < 2; mt++)
#pragma unroll
        for (int nt = 0; nt < 8; nt++)
#pragma unroll
            for (int i = 0; i < 4; i++) acc[mt][nt][i] = 0.f;

    const int NCH = K / 32;
    gemm_issue(sb,        A, B, bm, bn, 0,  K, N, tid); CP_COMMIT();
    gemm_issue(sb + GSTG, A, B, bm, bn, 32, K, N, tid); CP_COMMIT();

    for (int ch = 0; ch < NCH; ch++) {
        if (ch + 2 < NCH)
            gemm_issue(sb + ((ch + 2) % 3) * GSTG, A, B,
                       bm, bn, (ch + 2) * 32, K, N, tid);
        CP_COMMIT();
        CP_WAIT(2);
        __syncthreads();

        const uint32_t s0 = sb + (ch % 3) * GSTG;
#pragma unroll
        for (int ks = 0; ks < 2; ks++) {
            unsigned ah[2][4];
#pragma unroll
            for (int mt = 0; mt < 2; mt++) {
                int row = wm * 32 + mt * 16 + (m8 & 1) * 8 + ri;
                int c4  = 2 * ks + (m8 >> 1);
                uint32_t a = s0 + row * 64 + ((c4 ^ ((row >> 1) & 3)) << 4);
                ldsm4(ah[mt][0], ah[mt][1], ah[mt][2], ah[mt][3], a);
            }
#pragma unroll
            for (int ntp = 0; ntp < 4; ntp++) {
                int kr = 16 * ks + (m8 & 1) * 8 + ri;
                int cc = wn * 8 + ntp * 2 + (m8 >> 1);
                uint32_t ba = s0 + 8192 + kr * 256 + ((cc ^ (kr & 7)) << 4);
                unsigned bh[4];
                ldsm4t(bh[0], bh[1], bh[2], bh[3], ba);
                mma16(acc[0][ntp * 2 + 0], ah[0], bh[0], bh[1]);
                mma16(acc[1][ntp * 2 + 0], ah[1], bh[0], bh[1]);
                mma16(acc[0][ntp * 2 + 1], ah[0], bh[2], bh[3]);
                mma16(acc[1][ntp * 2 + 1], ah[1], bh[2], bh[3]);
            }
        }
        __syncthreads();
    }

    // ---- epilogue ----
    if (mode == 0) {
#pragma unroll
        for (int mt = 0; mt < 2; mt++) {
#pragma unroll
            for (int nt = 0; nt < 8; nt++) {
                const int row = bm + wm * 32 + mt * 16 + g;
                const int col = bn + wn * 64 + nt * 8 + 2 * t;
                *(float2*)&C[(size_t)row * N + col] =
                    make_float2(acc[mt][nt][0], acc[mt][nt][1]);
                *(float2*)&C[(size_t)(row + 8) * N + col] =
                    make_float2(acc[mt][nt][2], acc[mt][nt][3]);
            }
        }
    } else {
#pragma unroll
        for (int mt = 0; mt < 2; mt++) {
#pragma unroll
            for (int nt = 0; nt < 8; nt++) {
                const int row = bm + wm * 32 + mt * 16 + g;
                const int col = bn + wn * 64 + nt * 8 + 2 * t;
                const int sec = col >> 10, hh = (col >> 6) & 15, d = col & 63;
                const int bb = row >> 11, tok = row & 2047;
                size_t idx = (((size_t)bb * NHEAD + hh) * TQ + tok) * DHEAD + d;
                __half* p = (sec == 0) ? gQ : ((sec == 1) ? gK : gV);
                *(unsigned*)&p[idx] = round2h(acc[mt][nt][0], acc[mt][nt][1]);
                *(unsigned*)&p[idx + 8 * DHEAD] = round2h(acc[mt][nt][2], acc[mt][nt][3]);
            }
        }
    }
}

// =====================================================================
// Flash attention: fp16, base-2 softmax with ex2.approx.f16x2.
// 48KB smem, occ 2. Grid (NQT2, NHEAD, BATCH).
// =====================================================================
#define FKV0 16384
#define FSTG 16384

__device__ __forceinline__ void flash_issue_kv(uint32_t s0, size_t base, int j, int tid)
{
#pragma unroll
    for (int it = 0; it < 2; it++) {
        int id = tid + it * 256;
        int r = id >> 3, c = id & 7;
        uint32_t d = s0 + r * 128 + ((c ^ (r & 7)) << 4);
        size_t go = base + (size_t)(j * 64 + r) * DHEAD + c * 8;
        cpa16(d,        gK + go);
        cpa16(d + 8192, gV + go);
    }
}

__global__ __launch_bounds__(256, 2) void flash_h1()
{
    __shared__ float sred[64];
    const uint32_t sb = (uint32_t)__cvta_generic_to_shared(dsm);
    const int qt = (int)gridDim.x - 1 - (int)blockIdx.x;   // longest-first
    const int h = blockIdx.y, b = blockIdx.z;
    const int tid = threadIdx.x, lane = tid & 31, wid = tid >> 5;
    const int g = lane >> 2, t = lane & 3;
    const int m8 = lane >> 3, ri = lane & 7;
    const size_t base = (size_t)(b * NHEAD + h) * TQ * DHEAD;

    // ---- Q cp.async (128 rows x 64 fp16 = 16KB) ----
#pragma unroll
    for (int it = 0; it < 4; it++) {
        int id = tid + it * 256;
        int r = id >> 3, c = id & 7;
        uint32_t d = sb + r * 128 + ((c ^ (r & 7)) << 4);
        cpa16(d, gQ + base + (size_t)(qt * 128 + r) * DHEAD + c * 8);
    }
    CP_COMMIT();
    flash_issue_kv(sb + FKV0, base, 0, tid); CP_COMMIT();
    CP_WAIT(1);
    __syncthreads();

    // ---- hoist Q fragments ----
    unsigned qh[4][4];
#pragma unroll
    for (int ks = 0; ks < 4; ks++) {
        int row = wid * 16 + (m8 & 1) * 8 + ri;
        int c = 2 * ks + (m8 >> 1);
        uint32_t a = sb + row * 128 + ((c ^ (row & 7)) << 4);
        ldsm4(qh[ks][0], qh[ks][1], qh[ks][2], qh[ks][3], a);
    }

    float oc[8][4];
#pragma unroll
    for (int nt = 0; nt < 8; nt++)
#pragma unroll
        for (int i = 0; i < 4; i++) oc[nt][i] = 0.f;

    float m0 = -1e30f, m1 = -1e30f, l0s = 0.f, l1s = 0.f, aa0 = 0.f, aa1 = 0.f;
    const int rowbase = qt * 128 + wid * 16;
    const int nj = 2 * qt + 2;

    for (int j = 0; j < nj; j++) {
        if (j + 1 < nj) flash_issue_kv(sb + FKV0 + ((j + 1) & 1) * FSTG, base, j + 1, tid);
        CP_COMMIT();
        CP_WAIT(1);
        __syncthreads();
        const uint32_t kv = sb + FKV0 + (j & 1) * FSTG;

        // ---- S = Q K^T ----
        float sc[8][4];
#pragma unroll
        for (int nt = 0; nt < 8; nt++)
#pragma unroll
            for (int i = 0; i < 4; i++) sc[nt][i] = 0.f;

#pragma unroll
        for (int ks = 0; ks < 4; ks++) {
#pragma unroll
            for (int ntp = 0; ntp < 4; ntp++) {
                int kr = ntp * 16 + (m8 & 1) * 8 + ri;
                int c = 2 * ks + (m8 >> 1);
                uint32_t ka = kv + kr * 128 + ((c ^ (kr & 7)) << 4);
                unsigned kh[4];
                ldsm4(kh[0], kh[1], kh[2], kh[3], ka);
                mma16(sc[2 * ntp],     qh[ks], kh[0], kh[2]);
                mma16(sc[2 * ntp + 1], qh[ks], kh[1], kh[3]);
            }
        }

        // ---- scale to base-2 domain + causal mask ----
        const bool needmask = (j * 64 + 63) > rowbase;
#pragma unroll
        for (int nt = 0; nt < 8; nt++) {
#pragma unroll
            for (int cc = 0; cc < 4; cc++) {
                float v = sc[nt][cc] * SC2F;   // S/sqrt(d) * log2(e)
                if (needmask) {
                    int col = j * 64 + nt * 8 + 2 * t + (cc & 1);
                    int row = rowbase + g + ((cc >> 1) << 3);
                    if (col > row) v = -1e30f;
                }
                sc[nt][cc] = v;
            }
        }

        // ---- online softmax (base-2, f16x2 exp) + entropy ----
        float mt0 = -1e30f, mt1 = -1e30f;
#pragma unroll
        for (int nt = 0; nt < 8; nt++) {
            mt0 = fmaxf(mt0, fmaxf(sc[nt][0], sc[nt][1]));
            mt1 = fmaxf(mt1, fmaxf(sc[nt][2], sc[nt][3]));
        }
        mt0 = fmaxf(mt0, __shfl_xor_sync(0xffffffffu, mt0, 1));
        mt0 = fmaxf(mt0, __shfl_xor_sync(0xffffffffu, mt0, 2));
        mt1 = fmaxf(mt1, __shfl_xor_sync(0xffffffffu, mt1, 1));
        mt1 = fmaxf(mt1, __shfl_xor_sync(0xffffffffu, mt1, 2));

        const float mn0 = fmaxf(m0, mt0), mn1 = fmaxf(m1, mt1);
        const float ex0 = ex2f(m0 - mn0), ex1 = ex2f(m1 - mn1);
        const __half2 mn0h = __float2half2_rn(mn0);
        const __half2 mn1h = __float2half2_rn(mn1);

        unsigned ph0[8], ph1[8];   // packed p (fp16x2) — also the PV A-frags
        float ls0 = 0.f, ls1 = 0.f, as0 = 0.f, as1 = 0.f;
#pragma unroll
        for (int nt = 0; nt < 8; nt++) {
            __half2 h0 = __floats2half2_rn(sc[nt][0], sc[nt][1]);
            __half2 h1 = __floats2half2_rn(sc[nt][2], sc[nt][3]);
            __half2 d0 = __hsub2(h0, mn0h);
            __half2 d1 = __hsub2(h1, mn1h);
            unsigned p0 = ex2h2(*reinterpret_cast<unsigned*>(&d0));
            unsigned p1 = ex2h2(*reinterpret_cast<unsigned*>(&d1));
            ph0[nt] = p0; ph1[nt] = p1;
            float2 f0 = __half22float2(*reinterpret_cast<__half2*>(&p0));
            float2 f1 = __half22float2(*reinterpret_cast<__half2*>(&p1));
            ls0 += f0.x + f0.y;  ls1 += f1.x + f1.y;
            as0 += f0.x * sc[nt][0] + f0.y * sc[nt][1];
            as1 += f1.x * sc[nt][2] + f1.y * sc[nt][3];
        }
        ls0 += __shfl_xor_sync(0xffffffffu, ls0, 1);
        ls0 += __shfl_xor_sync(0xffffffffu, ls0, 2);
        ls1 += __shfl_xor_sync(0xffffffffu, ls1, 1);
        ls1 += __shfl_xor_sync(0xffffffffu, ls1, 2);
        as0 += __shfl_xor_sync(0xffffffffu, as0, 1);
        as0 += __shfl_xor_sync(0xffffffffu, as0, 2);
        as1 += __shfl_xor_sync(0xffffffffu, as1, 1);
        as1 += __shfl_xor_sync(0xffffffffu, as1, 2);

        l0s = l0s * ex0 + ls0;  aa0 = aa0 * ex0 + as0;  m0 = mn0;
        l1s = l1s * ex1 + ls1;  aa1 = aa1 * ex1 + as1;  m1 = mn1;

#pragma unroll
        for (int nt = 0; nt < 8; nt++) {
            oc[nt][0] *= ex0; oc[nt][1] *= ex0;
            oc[nt][2] *= ex1; oc[nt][3] *= ex1;
        }

        // ---- O += P @ V ----
#pragma unroll
        for (int ks = 0; ks < 4; ks++) {
            unsigned aH[4] = {ph0[2*ks], ph1[2*ks], ph0[2*ks+1], ph1[2*ks+1]};
#pragma unroll
            for (int ntp = 0; ntp < 4; ntp++) {
                int vr = 16 * ks + (m8 & 1) * 8 + ri;
                int c = ntp * 2 + (m8 >> 1);
                uint32_t va = kv + 8192 + vr * 128 + ((c ^ (vr & 7)) << 4);
                unsigned vh[4];
                ldsm4t(vh[0], vh[1], vh[2], vh[3], va);
                mma16(oc[2 * ntp],     aH, vh[0], vh[1]);
                mma16(oc[2 * ntp + 1], aH, vh[2], vh[3]);
            }
        }
        __syncthreads();
    }

    // ---- epilogue: write yatt fp16 ----
    const float inv0 = 1.f / l0s, inv1 = 1.f / l1s;
    const int trow = rowbase + g;
#pragma unroll
    for (int nt = 0; nt < 8; nt++) {
        const int col = h * DHEAD + nt * 8 + 2 * t;
        size_t idx = ((size_t)b * TQ + trow) * CDIM + col;
        *(unsigned*)&gY[idx] = round2h(oc[nt][0] * inv0, oc[nt][1] * inv0);
        *(unsigned*)&gY[idx + 8 * CDIM] = round2h(oc[nt][2] * inv1, oc[nt][3] * inv1);
    }

    // ---- entropy partial: H = ln2 * (m2 + log2 l - a2/l) per row ----
    if (t == 0) {
        float H = LN2F * ((m0 + __log2f(l0s) - aa0 / l0s)
                        + (m1 + __log2f(l1s) - aa1 / l1s));
        sred[wid * 8 + g] = H;
    }
    __syncthreads();
    if (tid == 0) {
        float s = 0.f;
#pragma unroll 8
        for (int r = 0; r < 64; r++) s += sred[r];
        g_ent[((size_t)b * NHEAD + h) * NQT2 + qt] = s;
    }
}

// =====================================================================
// launch
// =====================================================================
extern "C" void kernel_launch(void* const* d_in, const int* in_sizes, int n_in,
                              void* d_out, int out_size)
{
    const float* x      = (const float*)d_in[0];
    const float* w_attn = (const float*)d_in[1];
    const float* w_proj = (const float*)d_in[2];
    float* out = (float*)d_out;
    (void)in_sizes; (void)n_in;

    __half *xp, *wa, *wp, *yp;
    cudaGetSymbolAddress((void**)&xp, gX);
    cudaGetSymbolAddress((void**)&wa, gWA);
    cudaGetSymbolAddress((void**)&wp, gWP);
    cudaGetSymbolAddress((void**)&yp, gY);

    const int GEMM_SMEM  = 3 * GSTG;           // 49152
    const int FLASH_SMEM = FKV0 + 2 * FSTG;    // 49152
    cudaFuncSetAttribute(gemm_h1,
                         cudaFuncAttributeMaxDynamicSharedMemorySize, GEMM_SMEM);
    cudaFuncSetAttribute(flash_h1,
                         cudaFuncAttributeMaxDynamicSharedMemorySize, FLASH_SMEM);

    // 0) fused prep (one launch)
    {
        int total = NX4 + NA4 + NP4;
        prep_kernel<<<(total + 255) / 256, 256>>>(x, w_attn, w_proj);
    }
    // 1) qkv = x @ w_attn -> Q, K, V fp16 (mode 1)
    {
        dim3 grid(C3 / 128, (BATCH * TQ) / 128);
        gemm_h1<<<grid, 256, GEMM_SMEM>>>(xp, wa, nullptr,
                                          BATCH * TQ, C3, CDIM, 1, out_size);
    }
    // 2) flash attention + entropy partials -> gY
    {
        dim3 grid(NQT2, NHEAD, BATCH);
        flash_h1<<<grid, 256, FLASH_SMEM>>>();
    }
    // 3) y = yatt @ w_proj -> d_out (mode 0; block(0,0) also writes entropy)
    {
        dim3 grid(CDIM / 128, (BATCH * TQ) / 128);
        gemm_h1<<<grid, 256, GEMM_SMEM>>>(yp, wp, out,
                                          BATCH * TQ, CDIM, CDIM, 0, out_size);
    }
}

// round 11
// speedup vs baseline: 2.7918x; 1.1752x over previous
#include <cuda_runtime.h>
#include <cuda_fp16.h>
#include <stdint.h>

// ---------------- problem constants ----------------
#define BATCH  2
#define TQ     2048
#define CDIM   1024
#define NHEAD  16
#define DHEAD  64
#define C3     (3 * CDIM)
#define NQT2   (TQ / 128)
#define NROWS  (BATCH * NHEAD * TQ)
#define QKVN   (BATCH * NHEAD * TQ * DHEAD)
#define LN2F   0.6931471805599453f
#define SC2F   0.1803368801111601f   // 0.125 * log2(e)

// ---------------- fp16 planes (device scratch) ----------------
__device__ __align__(16) __half gX[BATCH*TQ*CDIM];
__device__ __align__(16) __half gWA[CDIM*C3];
__device__ __align__(16) __half gWP[CDIM*CDIM];
__device__ __align__(16) __half gQ[QKVN];
__device__ __align__(16) __half gK[QKVN];
__device__ __align__(16) __half gV[QKVN];
__device__ __align__(16) __half gY[BATCH*TQ*CDIM];
__device__ float g_ent[BATCH * NHEAD * NQT2];

// ---------------- helpers ----------------
__device__ __forceinline__ unsigned round2h(float a, float b) {
    __half2 h = __floats2half2_rn(a, b);
    return *reinterpret_cast<unsigned*>(&h);
}
__device__ __forceinline__ float ex2f(float x) {
    float r; asm("ex2.approx.f32 %0, %1;" : "=f"(r) : "f"(x)); return r;
}
__device__ __forceinline__ unsigned ex2h2(unsigned x) {
    unsigned r; asm("ex2.approx.f16x2 %0, %1;" : "=r"(r) : "r"(x)); return r;
}
__device__ __forceinline__ void mma16(float* c, const unsigned* a, unsigned b0, unsigned b1) {
    asm("mma.sync.aligned.m16n8k16.row.col.f32.f16.f16.f32 "
        "{%0,%1,%2,%3},{%4,%5,%6,%7},{%8,%9},{%0,%1,%2,%3};"
        : "+f"(c[0]), "+f"(c[1]), "+f"(c[2]), "+f"(c[3])
        : "r"(a[0]), "r"(a[1]), "r"(a[2]), "r"(a[3]), "r"(b0), "r"(b1));
}
__device__ __forceinline__ void ldsm4(unsigned& r0, unsigned& r1, unsigned& r2, unsigned& r3, uint32_t a) {
    asm volatile("ldmatrix.sync.aligned.m8n8.x4.shared.b16 {%0,%1,%2,%3},[%4];"
        : "=r"(r0), "=r"(r1), "=r"(r2), "=r"(r3) : "r"(a));
}
__device__ __forceinline__ void ldsm4t(unsigned& r0, unsigned& r1, unsigned& r2, unsigned& r3, uint32_t a) {
    asm volatile("ldmatrix.sync.aligned.m8n8.x4.trans.shared.b16 {%0,%1,%2,%3},[%4];"
        : "=r"(r0), "=r"(r1), "=r"(r2), "=r"(r3) : "r"(a));
}
__device__ __forceinline__ void cpa16(uint32_t d, const void* s) {
    asm volatile("cp.async.ca.shared.global [%0],[%1],16;" :: "r"(d), "l"(s));
}
#define CP_COMMIT() asm volatile("cp.async.commit_group;" ::: "memory")
#define CP_WAIT(N)  asm volatile("cp.async.wait_group %0;" :: "n"(N) : "memory")

// =====================================================================
// fused prep: round x, w_attn, w_proj to fp16; 4 float4 per thread
// =====================================================================
#define NX4 (BATCH * TQ * CDIM / 4)   // 1,048,576
#define NA4 (CDIM * C3 / 4)           //   786,432
#define NP4 (CDIM * CDIM / 4)         //   262,144
#define NT4 (NX4 + NA4 + NP4)         // 2,097,152
__global__ void prep_kernel(const float* __restrict__ x,
                            const float* __restrict__ wa,
                            const float* __restrict__ wp)
{
    int base = blockIdx.x * (blockDim.x * 4) + threadIdx.x;
#pragma unroll
    for (int u = 0; u < 4; u++) {
        int i = base + u * 256;
        if (i >= NT4) return;
        const float* in; __half* out; int j;
        if (i < NX4)            { in = x;  out = gX;  j = i; }
        else if (i < NX4 + NA4) { in = wa; out = gWA; j = i - NX4; }
        else                    { in = wp; out = gWP; j = i - NX4 - NA4; }
        float4 v = ((const float4*)in)[j];
        ((uint2*)out)[j] = make_uint2(round2h(v.x, v.y), round2h(v.z, v.w));
    }
}

// =====================================================================
// GEMM (fp16): C = A @ B. 128x128 tile, BK=32, 256 thr, 3-stage cp.async.
// mode 0: fp32 C (+ block(0,0) computes entropy scalar); mode 1: qkv scatter.
// =====================================================================
#define GSTG 16384
extern __shared__ char dsm[];

__device__ __forceinline__ void gemm_issue(
    uint32_t s0, const __half* A, const __half* B,
    int bm, int bn, int k0, int K, int N, int tid)
{
#pragma unroll
    for (int it = 0; it < 2; it++) {
        int id = tid + it * 256;
        int r = id >> 2, c = id & 3;
        uint32_t d = s0 + r * 64 + ((c ^ ((r >> 1) & 3)) << 4);
        cpa16(d, A + (size_t)(bm + r) * K + k0 + c * 8);
    }
#pragma unroll
    for (int it = 0; it < 2; it++) {
        int id = tid + it * 256;
        int k = id >> 4, c = id & 15;
        uint32_t d = s0 + 8192 + k * 256 + ((c ^ (k & 7)) << 4);
        cpa16(d, B + (size_t)(k0 + k) * N + bn + c * 8);
    }
}

__global__ __launch_bounds__(256, 2) void gemm_h1(
    const __half* __restrict__ A, const __half* __restrict__ B,
    float* __restrict__ C, int M, int N, int K, int mode, int out_size)
{
    const uint32_t sb = (uint32_t)__cvta_generic_to_shared(dsm);
    const int tid = threadIdx.x, lane = tid & 31, wid = tid >> 5;
    const int g = lane >> 2, t = lane & 3;
    const int m8 = lane >> 3, ri = lane & 7;
    const int wm = wid & 3, wn = wid >> 2;
    const int bm = blockIdx.y * 128, bn = blockIdx.x * 128;

    // ---- fused entropy scalar (proj launch only, one block) ----
    if (mode == 0 && blockIdx.x == 0 && blockIdx.y == 0) {
        __shared__ float red[256];
        float s = 0.f;
        for (int i = tid; i < BATCH * NHEAD * NQT2; i += 256) s += g_ent[i];
        red[tid] = s;
        __syncthreads();
        for (int st = 128; st > 0; st >>= 1) {
            if (tid < st) red[tid] += red[tid + st];
            __syncthreads();
        }
        if (tid == 0) C[out_size - 1] = red[0] / (float)NROWS;
    }

    float acc[2][8][4];
#pragma unroll
    for (int mt = 0; mt < 2; mt++)
#pragma unroll
        for (int nt = 0; nt < 8; nt++)
#pragma unroll
            for (int i = 0; i < 4; i++) acc[mt][nt][i] = 0.f;

    const int NCH = K / 32;
    gemm_issue(sb,        A, B, bm, bn, 0,  K, N, tid); CP_COMMIT();
    gemm_issue(sb + GSTG, A, B, bm, bn, 32, K, N, tid); CP_COMMIT();

    for (int ch = 0; ch < NCH; ch++) {
        if (ch + 2 < NCH)
            gemm_issue(sb + ((ch + 2) % 3) * GSTG, A, B,
                       bm, bn, (ch + 2) * 32, K, N, tid);
        CP_COMMIT();
        CP_WAIT(2);
        __syncthreads();

        const uint32_t s0 = sb + (ch % 3) * GSTG;
#pragma unroll
        for (int ks = 0; ks < 2; ks++) {
            unsigned ah[2][4];
#pragma unroll
            for (int mt = 0; mt < 2; mt++) {
                int row = wm * 32 + mt * 16 + (m8 & 1) * 8 + ri;
                int c4  = 2 * ks + (m8 >> 1);
                uint32_t a = s0 + row * 64 + ((c4 ^ ((row >> 1) & 3)) << 4);
                ldsm4(ah[mt][0], ah[mt][1], ah[mt][2], ah[mt][3], a);
            }
#pragma unroll
            for (int ntp = 0; ntp < 4; ntp++) {
                int kr = 16 * ks + (m8 & 1) * 8 + ri;
                int cc = wn * 8 + ntp * 2 + (m8 >> 1);
                uint32_t ba = s0 + 8192 + kr * 256 + ((cc ^ (kr & 7)) << 4);
                unsigned bh[4];
                ldsm4t(bh[0], bh[1], bh[2], bh[3], ba);
                mma16(acc[0][ntp * 2 + 0], ah[0], bh[0], bh[1]);
                mma16(acc[1][ntp * 2 + 0], ah[1], bh[0], bh[1]);
                mma16(acc[0][ntp * 2 + 1], ah[0], bh[2], bh[3]);
                mma16(acc[1][ntp * 2 + 1], ah[1], bh[2], bh[3]);
            }
        }
        __syncthreads();
    }

    // ---- epilogue ----
    if (mode == 0) {
#pragma unroll
        for (int mt = 0; mt < 2; mt++) {
#pragma unroll
            for (int nt = 0; nt < 8; nt++) {
                const int row = bm + wm * 32 + mt * 16 + g;
                const int col = bn + wn * 64 + nt * 8 + 2 * t;
                *(float2*)&C[(size_t)row * N + col] =
                    make_float2(acc[mt][nt][0], acc[mt][nt][1]);
                *(float2*)&C[(size_t)(row + 8) * N + col] =
                    make_float2(acc[mt][nt][2], acc[mt][nt][3]);
            }
        }
    } else {
#pragma unroll
        for (int mt = 0; mt < 2; mt++) {
#pragma unroll
            for (int nt = 0; nt < 8; nt++) {
                const int row = bm + wm * 32 + mt * 16 + g;
                const int col = bn + wn * 64 + nt * 8 + 2 * t;
                const int sec = col >> 10, hh = (col >> 6) & 15, d = col & 63;
                const int bb = row >> 11, tok = row & 2047;
                size_t idx = (((size_t)bb * NHEAD + hh) * TQ + tok) * DHEAD + d;
                __half* p = (sec == 0) ? gQ : ((sec == 1) ? gK : gV);
                *(unsigned*)&p[idx] = round2h(acc[mt][nt][0], acc[mt][nt][1]);
                *(unsigned*)&p[idx + 8 * DHEAD] = round2h(acc[mt][nt][2], acc[mt][nt][3]);
            }
        }
    }
}

// =====================================================================
// Flash attention: fp16, base-2 f16x2 softmax, 3-stage KV ring,
// ONE barrier per tile. 64KB smem, occ 2. 1D longest-first grid.
// =====================================================================
#define FKV0 16384
#define FSTG 16384

__device__ __forceinline__ void flash_issue_kv(uint32_t s0, size_t base, int j, int tid)
{
#pragma unroll
    for (int it = 0; it < 2; it++) {
        int id = tid + it * 256;
        int r = id >> 3, c = id & 7;
        uint32_t d = s0 + r * 128 + ((c ^ (r & 7)) << 4);
        size_t go = base + (size_t)(j * 64 + r) * DHEAD + c * 8;
        cpa16(d,        gK + go);
        cpa16(d + 8192, gV + go);
    }
}

__global__ __launch_bounds__(256, 2) void flash_h1()
{
    __shared__ float sred[64];
    const uint32_t sb = (uint32_t)__cvta_generic_to_shared(dsm);
    const int bid = (int)blockIdx.x;
    const int qt = NQT2 - 1 - (bid >> 5);     // global longest-first
    const int hb = bid & 31;
    const int h = hb & 15, b = hb >> 4;
    const int tid = threadIdx.x, lane = tid & 31, wid = tid >> 5;
    const int g = lane >> 2, t = lane & 3;
    const int m8 = lane >> 3, ri = lane & 7;
    const size_t base = (size_t)(b * NHEAD + h) * TQ * DHEAD;
    const int nj = 2 * qt + 2;

    // ---- prologue: Q + KV0 (group A), KV1 (group B) ----
#pragma unroll
    for (int it = 0; it < 4; it++) {
        int id = tid + it * 256;
        int r = id >> 3, c = id & 7;
        uint32_t d = sb + r * 128 + ((c ^ (r & 7)) << 4);
        cpa16(d, gQ + base + (size_t)(qt * 128 + r) * DHEAD + c * 8);
    }
    flash_issue_kv(sb + FKV0, base, 0, tid);
    CP_COMMIT();                               // A = Q + KV0
    flash_issue_kv(sb + FKV0 + FSTG, base, 1, tid);   // nj >= 2 always
    CP_COMMIT();                               // B = KV1
    CP_WAIT(1);                                // A complete
    __syncthreads();

    // ---- hoist Q fragments (Q region never overwritten) ----
    unsigned qh[4][4];
#pragma unroll
    for (int ks = 0; ks < 4; ks++) {
        int row = wid * 16 + (m8 & 1) * 8 + ri;
        int c = 2 * ks + (m8 >> 1);
        uint32_t a = sb + row * 128 + ((c ^ (row & 7)) << 4);
        ldsm4(qh[ks][0], qh[ks][1], qh[ks][2], qh[ks][3], a);
    }

    float oc[8][4];
#pragma unroll
    for (int nt = 0; nt < 8; nt++)
#pragma unroll
        for (int i = 0; i < 4; i++) oc[nt][i] = 0.f;

    float m0 = -1e30f, m1 = -1e30f, l0s = 0.f, l1s = 0.f, aa0 = 0.f, aa1 = 0.f;
    const int rowbase = qt * 128 + wid * 16;
    int st2 = 2;   // stage index of KV(j+2), cycles 2,0,1,...

    for (int j = 0; j < nj; j++) {
        // group j complete for THIS thread; barrier makes it block-wide AND
        // frees stage (j-1)%3 == (j+2)%3 for the prefetch below.
        CP_WAIT(1);
        __syncthreads();
        if (j + 2 < nj) flash_issue_kv(sb + FKV0 + st2 * FSTG, base, j + 2, tid);
        CP_COMMIT();
        const uint32_t kv = sb + FKV0 + (st2 == 2 ? 0 : st2 + 1) * FSTG;  // j%3
        st2 = (st2 == 2) ? 0 : st2 + 1;

        // ---- S = Q K^T ----
        float sc[8][4];
#pragma unroll
        for (int nt = 0; nt < 8; nt++)
#pragma unroll
            for (int i = 0; i < 4; i++) sc[nt][i] = 0.f;

#pragma unroll
        for (int ks = 0; ks < 4; ks++) {
#pragma unroll
            for (int ntp = 0; ntp < 4; ntp++) {
                int kr = ntp * 16 + (m8 & 1) * 8 + ri;
                int c = 2 * ks + (m8 >> 1);
                uint32_t ka = kv + kr * 128 + ((c ^ (kr & 7)) << 4);
                unsigned kh[4];
                ldsm4(kh[0], kh[1], kh[2], kh[3], ka);
                mma16(sc[2 * ntp],     qh[ks], kh[0], kh[2]);
                mma16(sc[2 * ntp + 1], qh[ks], kh[1], kh[3]);
            }
        }

        // ---- scale to base-2 domain + causal mask ----
        const bool needmask = (j * 64 + 63) > rowbase;
#pragma unroll
        for (int nt = 0; nt < 8; nt++) {
#pragma unroll
            for (int cc = 0; cc < 4; cc++) {
                float v = sc[nt][cc] * SC2F;
                if (needmask) {
                    int col = j * 64 + nt * 8 + 2 * t + (cc & 1);
                    int row = rowbase + g + ((cc >> 1) << 3);
                    if (col > row) v = -1e30f;
                }
                sc[nt][cc] = v;
            }
        }

        // ---- online softmax (base-2, f16x2 exp) + entropy ----
        float mt0 = -1e30f, mt1 = -1e30f;
#pragma unroll
        for (int nt = 0; nt < 8; nt++) {
            mt0 = fmaxf(mt0, fmaxf(sc[nt][0], sc[nt][1]));
            mt1 = fmaxf(mt1, fmaxf(sc[nt][2], sc[nt][3]));
        }
        mt0 = fmaxf(mt0, __shfl_xor_sync(0xffffffffu, mt0, 1));
        mt0 = fmaxf(mt0, __shfl_xor_sync(0xffffffffu, mt0, 2));
        mt1 = fmaxf(mt1, __shfl_xor_sync(0xffffffffu, mt1, 1));
        mt1 = fmaxf(mt1, __shfl_xor_sync(0xffffffffu, mt1, 2));

        const float mn0 = fmaxf(m0, mt0), mn1 = fmaxf(m1, mt1);
        const float ex0 = ex2f(m0 - mn0), ex1 = ex2f(m1 - mn1);
        const __half2 mn0h = __float2half2_rn(mn0);
        const __half2 mn1h = __float2half2_rn(mn1);

        unsigned ph0[8], ph1[8];
        float ls0 = 0.f, ls1 = 0.f, as0 = 0.f, as1 = 0.f;
#pragma unroll
        for (int nt = 0; nt < 8; nt++) {
            __half2 h0 = __floats2half2_rn(sc[nt][0], sc[nt][1]);
            __half2 h1 = __floats2half2_rn(sc[nt][2], sc[nt][3]);
            __half2 d0 = __hsub2(h0, mn0h);
            __half2 d1 = __hsub2(h1, mn1h);
            unsigned p0 = ex2h2(*reinterpret_cast<unsigned*>(&d0));
            unsigned p1 = ex2h2(*reinterpret_cast<unsigned*>(&d1));
            ph0[nt] = p0; ph1[nt] = p1;
            float2 f0 = __half22float2(*reinterpret_cast<__half2*>(&p0));
            float2 f1 = __half22float2(*reinterpret_cast<__half2*>(&p1));
            ls0 += f0.x + f0.y;  ls1 += f1.x + f1.y;
            as0 += f0.x * sc[nt][0] + f0.y * sc[nt][1];
            as1 += f1.x * sc[nt][2] + f1.y * sc[nt][3];
        }
        ls0 += __shfl_xor_sync(0xffffffffu, ls0, 1);
        ls0 += __shfl_xor_sync(0xffffffffu, ls0, 2);
        ls1 += __shfl_xor_sync(0xffffffffu, ls1, 1);
        ls1 += __shfl_xor_sync(0xffffffffu, ls1, 2);
        as0 += __shfl_xor_sync(0xffffffffu, as0, 1);
        as0 += __shfl_xor_sync(0xffffffffu, as0, 2);
        as1 += __shfl_xor_sync(0xffffffffu, as1, 1);
        as1 += __shfl_xor_sync(0xffffffffu, as1, 2);

        l0s = l0s * ex0 + ls0;  aa0 = aa0 * ex0 + as0;  m0 = mn0;
        l1s = l1s * ex1 + ls1;  aa1 = aa1 * ex1 + as1;  m1 = mn1;

#pragma unroll
        for (int nt = 0; nt < 8; nt++) {
            oc[nt][0] *= ex0; oc[nt][1] *= ex0;
            oc[nt][2] *= ex1; oc[nt][3] *= ex1;
        }

        // ---- O += P @ V ----
#pragma unroll
        for (int ks = 0; ks < 4; ks++) {
            unsigned aH[4] = {ph0[2*ks], ph1[2*ks], ph0[2*ks+1], ph1[2*ks+1]};
#pragma unroll
            for (int ntp = 0; ntp < 4; ntp++) {
                int vr = 16 * ks + (m8 & 1) * 8 + ri;
                int c = ntp * 2 + (m8 >> 1);
                uint32_t va = kv + 8192 + vr * 128 + ((c ^ (vr & 7)) << 4);
                unsigned vh[4];
                ldsm4t(vh[0], vh[1], vh[2], vh[3], va);
                mma16(oc[2 * ntp],     aH, vh[0], vh[1]);
                mma16(oc[2 * ntp + 1], aH, vh[2], vh[3]);
            }
        }
    }

    // ---- epilogue: write yatt fp16 ----
    const float inv0 = 1.f / l0s, inv1 = 1.f / l1s;
    const int trow = rowbase + g;
#pragma unroll
    for (int nt = 0; nt < 8; nt++) {
        const int col = h * DHEAD + nt * 8 + 2 * t;
        size_t idx = ((size_t)b * TQ + trow) * CDIM + col;
        *(unsigned*)&gY[idx] = round2h(oc[nt][0] * inv0, oc[nt][1] * inv0);
        *(unsigned*)&gY[idx + 8 * CDIM] = round2h(oc[nt][2] * inv1, oc[nt][3] * inv1);
    }

    // ---- entropy partial: H = ln2 * (m2 + log2 l - a2/l) per row ----
    if (t == 0) {
        float H = LN2F * ((m0 + __log2f(l0s) - aa0 / l0s)
                        + (m1 + __log2f(l1s) - aa1 / l1s));
        sred[wid * 8 + g] = H;
    }
    __syncthreads();
    if (tid == 0) {
        float s = 0.f;
#pragma unroll 8
        for (int r = 0; r < 64; r++) s += sred[r];
        g_ent[((size_t)b * NHEAD + h) * NQT2 + qt] = s;
    }
}

// =====================================================================
// launch
// =====================================================================
extern "C" void kernel_launch(void* const* d_in, const int* in_sizes, int n_in,
                              void* d_out, int out_size)
{
    const float* x      = (const float*)d_in[0];
    const float* w_attn = (const float*)d_in[1];
    const float* w_proj = (const float*)d_in[2];
    float* out = (float*)d_out;
    (void)in_sizes; (void)n_in;

    __half *xp, *wa, *wp, *yp;
    cudaGetSymbolAddress((void**)&xp, gX);
    cudaGetSymbolAddress((void**)&wa, gWA);
    cudaGetSymbolAddress((void**)&wp, gWP);
    cudaGetSymbolAddress((void**)&yp, gY);

    const int GEMM_SMEM  = 3 * GSTG;           // 49152
    const int FLASH_SMEM = FKV0 + 3 * FSTG;    // 65536
    cudaFuncSetAttribute(gemm_h1,
                         cudaFuncAttributeMaxDynamicSharedMemorySize, GEMM_SMEM);
    cudaFuncSetAttribute(flash_h1,
                         cudaFuncAttributeMaxDynamicSharedMemorySize, FLASH_SMEM);

    // 0) fused prep (one launch, 4 float4/thread)
    {
        int blocks = (NT4 + 1023) / 1024;
        prep_kernel<<<blocks, 256>>>(x, w_attn, w_proj);
    }
    // 1) qkv = x @ w_attn -> Q, K, V fp16 (mode 1)
    {
        dim3 grid(C3 / 128, (BATCH * TQ) / 128);
        gemm_h1<<<grid, 256, GEMM_SMEM>>>(xp, wa, nullptr,
                                          BATCH * TQ, C3, CDIM, 1, out_size);
    }
    // 2) flash attention (1D longest-first grid) -> gY + entropy partials
    {
        flash_h1<<<NQT2 * NHEAD * BATCH, 256, FLASH_SMEM>>>();
    }
    // 3) y = yatt @ w_proj -> d_out (mode 0; block(0,0) also writes entropy)
    {
        dim3 grid(CDIM / 128, (BATCH * TQ) / 128);
        gemm_h1<<<grid, 256, GEMM_SMEM>>>(yp, wp, out,
                                          BATCH * TQ, CDIM, CDIM, 0, out_size);
    }
}

// round 12
// speedup vs baseline: 2.8723x; 1.0288x over previous
#include <cuda_runtime.h>
#include <cuda_fp16.h>
#include <stdint.h>

// ---------------- problem constants ----------------
#define BATCH  2
#define TQ     2048
#define CDIM   1024
#define NHEAD  16
#define DHEAD  64
#define C3     (3 * CDIM)
#define NQT2   (TQ / 128)
#define NROWS  (BATCH * NHEAD * TQ)
#define QKVN   (BATCH * NHEAD * TQ * DHEAD)
#define LN2F   0.6931471805599453f
#define SC2F   0.1803368801111601f   // 0.125 * log2(e)

// ---------------- fp16 planes (device scratch) ----------------
__device__ __align__(16) __half gX[BATCH*TQ*CDIM];
__device__ __align__(16) __half gWA[CDIM*C3];
__device__ __align__(16) __half gWP[CDIM*CDIM];
__device__ __align__(16) __half gQ[QKVN];   // stored PRE-SCALED by SC2F
__device__ __align__(16) __half gK[QKVN];
__device__ __align__(16) __half gV[QKVN];
__device__ __align__(16) __half gY[BATCH*TQ*CDIM];
__device__ float g_ent[BATCH * NHEAD * NQT2];

// ---------------- helpers ----------------
__device__ __forceinline__ unsigned round2h(float a, float b) {
    __half2 h = __floats2half2_rn(a, b);
    return *reinterpret_cast<unsigned*>(&h);
}
__device__ __forceinline__ float ex2f(float x) {
    float r; asm("ex2.approx.f32 %0, %1;" : "=f"(r) : "f"(x)); return r;
}
__device__ __forceinline__ unsigned ex2h2(unsigned x) {
    unsigned r; asm("ex2.approx.f16x2 %0, %1;" : "=r"(r) : "r"(x)); return r;
}
__device__ __forceinline__ void mma16(float* c, const unsigned* a, unsigned b0, unsigned b1) {
    asm("mma.sync.aligned.m16n8k16.row.col.f32.f16.f16.f32 "
        "{%0,%1,%2,%3},{%4,%5,%6,%7},{%8,%9},{%0,%1,%2,%3};"
        : "+f"(c[0]), "+f"(c[1]), "+f"(c[2]), "+f"(c[3])
        : "r"(a[0]), "r"(a[1]), "r"(a[2]), "r"(a[3]), "r"(b0), "r"(b1));
}
__device__ __forceinline__ void ldsm4(unsigned& r0, unsigned& r1, unsigned& r2, unsigned& r3, uint32_t a) {
    asm volatile("ldmatrix.sync.aligned.m8n8.x4.shared.b16 {%0,%1,%2,%3},[%4];"
        : "=r"(r0), "=r"(r1), "=r"(r2), "=r"(r3) : "r"(a));
}
__device__ __forceinline__ void ldsm4t(unsigned& r0, unsigned& r1, unsigned& r2, unsigned& r3, uint32_t a) {
    asm volatile("ldmatrix.sync.aligned.m8n8.x4.trans.shared.b16 {%0,%1,%2,%3},[%4];"
        : "=r"(r0), "=r"(r1), "=r"(r2), "=r"(r3) : "r"(a));
}
__device__ __forceinline__ void cpa16(uint32_t d, const void* s) {
    asm volatile("cp.async.ca.shared.global [%0],[%1],16;" :: "r"(d), "l"(s));
}
#define CP_COMMIT() asm volatile("cp.async.commit_group;" ::: "memory")
#define CP_WAIT(N)  asm volatile("cp.async.wait_group %0;" :: "n"(N) : "memory")

// =====================================================================
// fused prep: round x, w_attn, w_proj to fp16; 4 float4 per thread
// =====================================================================
#define NX4 (BATCH * TQ * CDIM / 4)
#define NA4 (CDIM * C3 / 4)
#define NP4 (CDIM * CDIM / 4)
#define NT4 (NX4 + NA4 + NP4)
__global__ void prep_kernel(const float* __restrict__ x,
                            const float* __restrict__ wa,
                            const float* __restrict__ wp)
{
    int base = blockIdx.x * (blockDim.x * 4) + threadIdx.x;
#pragma unroll
    for (int u = 0; u < 4; u++) {
        int i = base + u * 256;
        if (i >= NT4) return;
        const float* in; __half* out; int j;
        if (i < NX4)            { in = x;  out = gX;  j = i; }
        else if (i < NX4 + NA4) { in = wa; out = gWA; j = i - NX4; }
        else                    { in = wp; out = gWP; j = i - NX4 - NA4; }
        float4 v = ((const float4*)in)[j];
        ((uint2*)out)[j] = make_uint2(round2h(v.x, v.y), round2h(v.z, v.w));
    }
}

// =====================================================================
// GEMM (fp16): C = A @ B. 128x128 tile, BK=32, 256 thr, 3-stage cp.async.
// mode 0: fp32 C (+ block(0,0) entropy); mode 1: qkv scatter (Q pre-scaled).
// =====================================================================
#define GSTG 16384
extern __shared__ char dsm[];

__device__ __forceinline__ void gemm_issue(
    uint32_t s0, const __half* A, const __half* B,
    int bm, int bn, int k0, int K, int N, int tid)
{
#pragma unroll
    for (int it = 0; it < 2; it++) {
        int id = tid + it * 256;
        int r = id >> 2, c = id & 3;
        uint32_t d = s0 + r * 64 + ((c ^ ((r >> 1) & 3)) << 4);
        cpa16(d, A + (size_t)(bm + r) * K + k0 + c * 8);
    }
#pragma unroll
    for (int it = 0; it < 2; it++) {
        int id = tid + it * 256;
        int k = id >> 4, c = id & 15;
        uint32_t d = s0 + 8192 + k * 256 + ((c ^ (k & 7)) << 4);
        cpa16(d, B + (size_t)(k0 + k) * N + bn + c * 8);
    }
}

__global__ __launch_bounds__(256, 2) void gemm_h1(
    const __half* __restrict__ A, const __half* __restrict__ B,
    float* __restrict__ C, int M, int N, int K, int mode, int out_size)
{
    const uint32_t sb = (uint32_t)__cvta_generic_to_shared(dsm);
    const int tid = threadIdx.x, lane = tid & 31, wid = tid >> 5;
    const int g = lane >> 2, t = lane & 3;
    const int m8 = lane >> 3, ri = lane & 7;
    const int wm = wid & 3, wn = wid >> 2;
    const int bm = blockIdx.y * 128, bn = blockIdx.x * 128;

    if (mode == 0 && blockIdx.x == 0 && blockIdx.y == 0) {
        __shared__ float red[256];
        float s = 0.f;
        for (int i = tid; i < BATCH * NHEAD * NQT2; i += 256) s += g_ent[i];
        red[tid] = s;
        __syncthreads();
        for (int st = 128; st > 0; st >>= 1) {
            if (tid < st) red[tid] += red[tid + st];
            __syncthreads();
        }
        if (tid == 0) C[out_size - 1] = red[0] / (float)NROWS;
    }

    float acc[2][8][4];
#pragma unroll
    for (int mt = 0; mt < 2; mt++)
#pragma unroll
        for (int nt = 0; nt < 8; nt++)
#pragma unroll
            for (int i = 0; i < 4; i++) acc[mt][nt][i] = 0.f;

    const int NCH = K / 32;
    gemm_issue(sb,        A, B, bm, bn, 0,  K, N, tid); CP_COMMIT();
    gemm_issue(sb + GSTG, A, B, bm, bn, 32, K, N, tid); CP_COMMIT();

    for (int ch = 0; ch < NCH; ch++) {
        if (ch + 2 < NCH)
            gemm_issue(sb + ((ch + 2) % 3) * GSTG, A, B,
                       bm, bn, (ch + 2) * 32, K, N, tid);
        CP_COMMIT();
        CP_WAIT(2);
        __syncthreads();

        const uint32_t s0 = sb + (ch % 3) * GSTG;
#pragma unroll
        for (int ks = 0; ks < 2; ks++) {
            unsigned ah[2][4];
#pragma unroll
            for (int mt = 0; mt < 2; mt++) {
                int row = wm * 32 + mt * 16 + (m8 & 1) * 8 + ri;
                int c4  = 2 * ks + (m8 >> 1);
                uint32_t a = s0 + row * 64 + ((c4 ^ ((row >> 1) & 3)) << 4);
                ldsm4(ah[mt][0], ah[mt][1], ah[mt][2], ah[mt][3], a);
            }
#pragma unroll
            for (int ntp = 0; ntp < 4; ntp++) {
                int kr = 16 * ks + (m8 & 1) * 8 + ri;
                int cc = wn * 8 + ntp * 2 + (m8 >> 1);
                uint32_t ba = s0 + 8192 + kr * 256 + ((cc ^ (kr & 7)) << 4);
                unsigned bh[4];
                ldsm4t(bh[0], bh[1], bh[2], bh[3], ba);
                mma16(acc[0][ntp * 2 + 0], ah[0], bh[0], bh[1]);
                mma16(acc[1][ntp * 2 + 0], ah[1], bh[0], bh[1]);
                mma16(acc[0][ntp * 2 + 1], ah[0], bh[2], bh[3]);
                mma16(acc[1][ntp * 2 + 1], ah[1], bh[2], bh[3]);
            }
        }
        __syncthreads();
    }

    // ---- epilogue ----
    if (mode == 0) {
#pragma unroll
        for (int mt = 0; mt < 2; mt++) {
#pragma unroll
            for (int nt = 0; nt < 8; nt++) {
                const int row = bm + wm * 32 + mt * 16 + g;
                const int col = bn + wn * 64 + nt * 8 + 2 * t;
                *(float2*)&C[(size_t)row * N + col] =
                    make_float2(acc[mt][nt][0], acc[mt][nt][1]);
                *(float2*)&C[(size_t)(row + 8) * N + col] =
                    make_float2(acc[mt][nt][2], acc[mt][nt][3]);
            }
        }
    } else {
#pragma unroll
        for (int mt = 0; mt < 2; mt++) {
#pragma unroll
            for (int nt = 0; nt < 8; nt++) {
                const int row = bm + wm * 32 + mt * 16 + g;
                const int col = bn + wn * 64 + nt * 8 + 2 * t;
                const int sec = col >> 10, hh = (col >> 6) & 15, d = col & 63;
                const int bb = row >> 11, tok = row & 2047;
                size_t idx = (((size_t)bb * NHEAD + hh) * TQ + tok) * DHEAD + d;
                __half* p = (sec == 0) ? gQ : ((sec == 1) ? gK : gV);
                const float sc = (sec == 0) ? SC2F : 1.f;   // pre-scale Q
                *(unsigned*)&p[idx] =
                    round2h(acc[mt][nt][0] * sc, acc[mt][nt][1] * sc);
                *(unsigned*)&p[idx + 8 * DHEAD] =
                    round2h(acc[mt][nt][2] * sc, acc[mt][nt][3] * sc);
            }
        }
    }
}

// =====================================================================
// Flash attention: fp16, base-2 f16x2 softmax, 3-stage KV ring,
// one barrier/tile, inactive-warp skip + diag-only mask. 64KB smem, occ 2.
// =====================================================================
#define FKV0 16384
#define FSTG 16384

__device__ __forceinline__ void flash_issue_kv(uint32_t s0, size_t base, int j, int tid)
{
#pragma unroll
    for (int it = 0; it < 2; it++) {
        int id = tid + it * 256;
        int r = id >> 3, c = id & 7;
        uint32_t d = s0 + r * 128 + ((c ^ (r & 7)) << 4);
        size_t go = base + (size_t)(j * 64 + r) * DHEAD + c * 8;
        cpa16(d,        gK + go);
        cpa16(d + 8192, gV + go);
    }
}

__global__ __launch_bounds__(256, 2) void flash_h1()
{
    __shared__ float sred[64];
    const uint32_t sb = (uint32_t)__cvta_generic_to_shared(dsm);
    const int bid = (int)blockIdx.x;
    const int qt = NQT2 - 1 - (bid >> 5);     // global longest-first
    const int hb = bid & 31;
    const int h = hb & 15, b = hb >> 4;
    const int tid = threadIdx.x, lane = tid & 31, wid = tid >> 5;
    const int g = lane >> 2, t = lane & 3;
    const int m8 = lane >> 3, ri = lane & 7;
    const size_t base = (size_t)(b * NHEAD + h) * TQ * DHEAD;
    const int nj = 2 * qt + 2;

    // ---- prologue: Q + KV0 (group A), KV1 (group B) ----
#pragma unroll
    for (int it = 0; it < 4; it++) {
        int id = tid + it * 256;
        int r = id >> 3, c = id & 7;
        uint32_t d = sb + r * 128 + ((c ^ (r & 7)) << 4);
        cpa16(d, gQ + base + (size_t)(qt * 128 + r) * DHEAD + c * 8);
    }
    flash_issue_kv(sb + FKV0, base, 0, tid);
    CP_COMMIT();
    flash_issue_kv(sb + FKV0 + FSTG, base, 1, tid);
    CP_COMMIT();
    CP_WAIT(1);
    __syncthreads();

    // ---- hoist Q fragments ----
    unsigned qh[4][4];
#pragma unroll
    for (int ks = 0; ks < 4; ks++) {
        int row = wid * 16 + (m8 & 1) * 8 + ri;
        int c = 2 * ks + (m8 >> 1);
        uint32_t a = sb + row * 128 + ((c ^ (row & 7)) << 4);
        ldsm4(qh[ks][0], qh[ks][1], qh[ks][2], qh[ks][3], a);
    }

    float oc[8][4];
#pragma unroll
    for (int nt = 0; nt < 8; nt++)
#pragma unroll
        for (int i = 0; i < 4; i++) oc[nt][i] = 0.f;

    float m0 = -1e30f, m1 = -1e30f, l0s = 0.f, l1s = 0.f, aa0 = 0.f, aa1 = 0.f;
    const int rowbase = qt * 128 + wid * 16;
    int st2 = 2;

    for (int j = 0; j < nj; j++) {
        CP_WAIT(1);
        __syncthreads();
        if (j + 2 < nj) flash_issue_kv(sb + FKV0 + st2 * FSTG, base, j + 2, tid);
        CP_COMMIT();
        const uint32_t kv = sb + FKV0 + (st2 == 2 ? 0 : st2 + 1) * FSTG;
        st2 = (st2 == 2) ? 0 : st2 + 1;

        // warp fully masked for this tile? (all cols > all rows) -> skip
        const bool active = (rowbase + 16) > (j * 64);
        if (!active) continue;

        // ---- S = Q K^T  (Q pre-scaled: sc is already base-2 domain) ----
        float sc[8][4];
#pragma unroll
        for (int nt = 0; nt < 8; nt++)
#pragma unroll
            for (int i = 0; i < 4; i++) sc[nt][i] = 0.f;

#pragma unroll
        for (int ks = 0; ks < 4; ks++) {
#pragma unroll
            for (int ntp = 0; ntp < 4; ntp++) {
                int kr = ntp * 16 + (m8 & 1) * 8 + ri;
                int c = 2 * ks + (m8 >> 1);
                uint32_t ka = kv + kr * 128 + ((c ^ (kr & 7)) << 4);
                unsigned kh[4];
                ldsm4(kh[0], kh[1], kh[2], kh[3], ka);
                mma16(sc[2 * ntp],     qh[ks], kh[0], kh[2]);
                mma16(sc[2 * ntp + 1], qh[ks], kh[1], kh[3]);
            }
        }

        // ---- causal mask: diagonal tiles only ----
        if ((j * 64 + 63) > rowbase) {
#pragma unroll
            for (int nt = 0; nt < 8; nt++) {
#pragma unroll
                for (int cc = 0; cc < 4; cc++) {
                    int col = j * 64 + nt * 8 + 2 * t + (cc & 1);
                    int row = rowbase + g + ((cc >> 1) << 3);
                    if (col > row) sc[nt][cc] = -1e30f;
                }
            }
        }

        // ---- online softmax (base-2, f16x2 exp) + entropy ----
        float mt0 = -1e30f, mt1 = -1e30f;
#pragma unroll
        for (int nt = 0; nt < 8; nt++) {
            mt0 = fmaxf(mt0, fmaxf(sc[nt][0], sc[nt][1]));
            mt1 = fmaxf(mt1, fmaxf(sc[nt][2], sc[nt][3]));
        }
        mt0 = fmaxf(mt0, __shfl_xor_sync(0xffffffffu, mt0, 1));
        mt0 = fmaxf(mt0, __shfl_xor_sync(0xffffffffu, mt0, 2));
        mt1 = fmaxf(mt1, __shfl_xor_sync(0xffffffffu, mt1, 1));
        mt1 = fmaxf(mt1, __shfl_xor_sync(0xffffffffu, mt1, 2));

        const float mn0 = fmaxf(m0, mt0), mn1 = fmaxf(m1, mt1);
        const float ex0 = ex2f(m0 - mn0), ex1 = ex2f(m1 - mn1);
        const __half2 mn0h = __float2half2_rn(mn0);
        const __half2 mn1h = __float2half2_rn(mn1);

        unsigned ph0[8], ph1[8];
        float ls0 = 0.f, ls1 = 0.f, as0 = 0.f, as1 = 0.f;
#pragma unroll
        for (int nt = 0; nt < 8; nt++) {
            __half2 h0 = __floats2half2_rn(sc[nt][0], sc[nt][1]);
            __half2 h1 = __floats2half2_rn(sc[nt][2], sc[nt][3]);
            __half2 d0 = __hsub2(h0, mn0h);
            __half2 d1 = __hsub2(h1, mn1h);
            unsigned p0 = ex2h2(*reinterpret_cast<unsigned*>(&d0));
            unsigned p1 = ex2h2(*reinterpret_cast<unsigned*>(&d1));
            ph0[nt] = p0; ph1[nt] = p1;
            float2 f0 = __half22float2(*reinterpret_cast<__half2*>(&p0));
            float2 f1 = __half22float2(*reinterpret_cast<__half2*>(&p1));
            ls0 += f0.x + f0.y;  ls1 += f1.x + f1.y;
            as0 += f0.x * sc[nt][0] + f0.y * sc[nt][1];
            as1 += f1.x * sc[nt][2] + f1.y * sc[nt][3];
        }
        ls0 += __shfl_xor_sync(0xffffffffu, ls0, 1);
        ls0 += __shfl_xor_sync(0xffffffffu, ls0, 2);
        ls1 += __shfl_xor_sync(0xffffffffu, ls1, 1);
        ls1 += __shfl_xor_sync(0xffffffffu, ls1, 2);
        as0 += __shfl_xor_sync(0xffffffffu, as0, 1);
        as0 += __shfl_xor_sync(0xffffffffu, as0, 2);
        as1 += __shfl_xor_sync(0xffffffffu, as1, 1);
        as1 += __shfl_xor_sync(0xffffffffu, as1, 2);

        l0s = l0s * ex0 + ls0;  aa0 = aa0 * ex0 + as0;  m0 = mn0;
        l1s = l1s * ex1 + ls1;  aa1 = aa1 * ex1 + as1;  m1 = mn1;

#pragma unroll
        for (int nt = 0; nt < 8; nt++) {
            oc[nt][0] *= ex0; oc[nt][1] *= ex0;
            oc[nt][2] *= ex1; oc[nt][3] *= ex1;
        }

        // ---- O += P @ V ----
#pragma unroll
        for (int ks = 0; ks < 4; ks++) {
            unsigned aH[4] = {ph0[2*ks], ph1[2*ks], ph0[2*ks+1], ph1[2*ks+1]};
#pragma unroll
            for (int ntp = 0; ntp < 4; ntp++) {
                int vr = 16 * ks + (m8 & 1) * 8 + ri;
                int c = ntp * 2 + (m8 >> 1);
                uint32_t va = kv + 8192 + vr * 128 + ((c ^ (vr & 7)) << 4);
                unsigned vh[4];
                ldsm4t(vh[0], vh[1], vh[2], vh[3], va);
                mma16(oc[2 * ntp],     aH, vh[0], vh[1]);
                mma16(oc[2 * ntp + 1], aH, vh[2], vh[3]);
            }
        }
    }

    // ---- epilogue: write yatt fp16 ----
    const float inv0 = 1.f / l0s, inv1 = 1.f / l1s;
    const int trow = rowbase + g;
#pragma unroll
    for (int nt = 0; nt < 8; nt++) {
        const int col = h * DHEAD + nt * 8 + 2 * t;
        size_t idx = ((size_t)b * TQ + trow) * CDIM + col;
        *(unsigned*)&gY[idx] = round2h(oc[nt][0] * inv0, oc[nt][1] * inv0);
        *(unsigned*)&gY[idx + 8 * CDIM] = round2h(oc[nt][2] * inv1, oc[nt][3] * inv1);
    }

    // ---- entropy partial: H = ln2 * (m2 + log2 l - a2/l) per row ----
    if (t == 0) {
        float H = LN2F * ((m0 + __log2f(l0s) - aa0 / l0s)
                        + (m1 + __log2f(l1s) - aa1 / l1s));
        sred[wid * 8 + g] = H;
    }
    __syncthreads();
    if (tid == 0) {
        float s = 0.f;
#pragma unroll 8
        for (int r = 0; r < 64; r++) s += sred[r];
        g_ent[((size_t)b * NHEAD + h) * NQT2 + qt] = s;
    }
}

// =====================================================================
// launch
// =====================================================================
extern "C" void kernel_launch(void* const* d_in, const int* in_sizes, int n_in,
                              void* d_out, int out_size)
{
    const float* x      = (const float*)d_in[0];
    const float* w_attn = (const float*)d_in[1];
    const float* w_proj = (const float*)d_in[2];
    float* out = (float*)d_out;
    (void)in_sizes; (void)n_in;

    __half *xp, *wa, *wp, *yp;
    cudaGetSymbolAddress((void**)&xp, gX);
    cudaGetSymbolAddress((void**)&wa, gWA);
    cudaGetSymbolAddress((void**)&wp, gWP);
    cudaGetSymbolAddress((void**)&yp, gY);

    const int GEMM_SMEM  = 3 * GSTG;           // 49152
    const int FLASH_SMEM = FKV0 + 3 * FSTG;    // 65536
    cudaFuncSetAttribute(gemm_h1,
                         cudaFuncAttributeMaxDynamicSharedMemorySize, GEMM_SMEM);
    cudaFuncSetAttribute(flash_h1,
                         cudaFuncAttributeMaxDynamicSharedMemorySize, FLASH_SMEM);

    // 0) fused prep
    {
        int blocks = (NT4 + 1023) / 1024;
        prep_kernel<<<blocks, 256>>>(x, w_attn, w_proj);
    }
    // 1) qkv = x @ w_attn -> Q (pre-scaled), K, V fp16
    {
        dim3 grid(C3 / 128, (BATCH * TQ) / 128);
        gemm_h1<<<grid, 256, GEMM_SMEM>>>(xp, wa, nullptr,
                                          BATCH * TQ, C3, CDIM, 1, out_size);
    }
    // 2) flash attention (1D longest-first grid) -> gY + entropy partials
    {
        flash_h1<<<NQT2 * NHEAD * BATCH, 256, FLASH_SMEM>>>();
    }
    // 3) y = yatt @ w_proj -> d_out (block(0,0) also writes entropy)
    {
        dim3 grid(CDIM / 128, (BATCH * TQ) / 128);
        gemm_h1<<<grid, 256, GEMM_SMEM>>>(yp, wp, out,
                                          BATCH * TQ, CDIM, CDIM, 0, out_size);
    }
}